// round 1
// baseline (speedup 1.0000x reference)
#include <cuda_runtime.h>
#include <cstddef>

#define BATCH 8
#define HW    4096
#define NK    256
#define DIM   512
#define NH    8
#define HD    64

// ---------------- scratch (no allocation allowed) ----------------
__device__ float g_q [2048u  * 512u];
__device__ float g_k [32768u * 512u];
__device__ float g_v [32768u * 512u];
__device__ float g_ao[2048u  * 512u];
__device__ float g_x [2048u  * 512u];
__device__ float g_attn_fb[(size_t)64 * 256 * 4096];  // fallback if attn not in d_out

// =================================================================
// 128x128x16 SGEMM, 256 threads, 8x8 microtile.
// HID_A=false: C[m,j] = sum_c A[m*512+c] * W[c*512+j] + bias[j] (+resid)
// HID_A=true : A is hidden (b, c, n): A elem (m=b*4096+n, c) = hid[b*512*4096 + c*4096 + n]
// N fixed = 512, K fixed = 512.
// Smem layout: As[m][c] / Bs[j][c], pad 18 -> conflict-free stores, ~2-way read max.
// =================================================================
template<bool HID_A>
__global__ void gemm128(const float* __restrict__ A, const float* __restrict__ W,
                        const float* __restrict__ bias, const float* __restrict__ resid,
                        float* __restrict__ C) {
    __shared__ float As[128][18];
    __shared__ float Bs[128][18];
    const int tid = threadIdx.x;
    const int tx = tid & 15, ty = tid >> 4;
    const int m0 = blockIdx.y * 128, j0 = blockIdx.x * 128;
    float acc[8][8];
    #pragma unroll
    for (int i = 0; i < 8; i++)
        #pragma unroll
        for (int j = 0; j < 8; j++) acc[i][j] = 0.f;

    for (int c0 = 0; c0 < 512; c0 += 16) {
        if (HID_A) {
            const int bb = m0 >> 12, n0 = m0 & 4095;
            #pragma unroll
            for (int i = 0; i < 8; i++) {
                int idx = tid + i * 256;
                int c = idx >> 7, m = idx & 127;                    // m fastest: coalesced in n
                As[m][c] = A[((size_t)bb * DIM + c0 + c) * HW + n0 + m];
            }
        } else {
            #pragma unroll
            for (int i = 0; i < 8; i++) {
                int idx = tid + i * 256;
                int m = idx >> 4, c = idx & 15;                     // c fastest
                As[m][c] = A[(size_t)(m0 + m) * 512 + c0 + c];
            }
        }
        #pragma unroll
        for (int i = 0; i < 8; i++) {
            int idx = tid + i * 256;
            int c = idx >> 7, j = idx & 127;                        // j fastest: coalesced
            Bs[j][c] = W[(size_t)(c0 + c) * 512 + j0 + j];
        }
        __syncthreads();
        #pragma unroll
        for (int c = 0; c < 16; c++) {
            float ra[8], rb[8];
            #pragma unroll
            for (int i = 0; i < 8; i++) ra[i] = As[ty * 8 + i][c];
            #pragma unroll
            for (int j = 0; j < 8; j++) rb[j] = Bs[tx * 8 + j][c];
            #pragma unroll
            for (int i = 0; i < 8; i++)
                #pragma unroll
                for (int j = 0; j < 8; j++) acc[i][j] += ra[i] * rb[j];
        }
        __syncthreads();
    }
    #pragma unroll
    for (int i = 0; i < 8; i++) {
        const int m = m0 + ty * 8 + i;
        #pragma unroll
        for (int j = 0; j < 8; j++) {
            const int jj = j0 + tx * 8 + j;
            float v = acc[i][j] + bias[jj];
            if (resid) v += resid[(size_t)m * 512 + jj];
            C[(size_t)m * 512 + jj] = v;
        }
    }
}

// =================================================================
// Scores: per (b,h): S[k,n] = 0.125 * sum_d Q[k,d]*K[n,d]   (NT GEMM, Kdim=64)
// grid: (ntile=32, mtile=2, bh=64)
// =================================================================
__global__ void gemm_nt_scores(const float* __restrict__ gq, const float* __restrict__ gk,
                               float* __restrict__ attn) {
    __shared__ float As[128][18];
    __shared__ float Bs[128][18];
    const int tid = threadIdx.x;
    const int tx = tid & 15, ty = tid >> 4;
    const int z = blockIdx.z, b = z >> 3, h = z & 7;
    const int m0 = blockIdx.y * 128, j0 = blockIdx.x * 128;
    const float* Aq = gq + (size_t)b * NK * DIM + h * HD;   // row stride 512
    const float* Bk = gk + (size_t)b * HW * DIM + h * HD;   // row stride 512
    float acc[8][8];
    #pragma unroll
    for (int i = 0; i < 8; i++)
        #pragma unroll
        for (int j = 0; j < 8; j++) acc[i][j] = 0.f;

    for (int c0 = 0; c0 < 64; c0 += 16) {
        #pragma unroll
        for (int i = 0; i < 8; i++) {
            int idx = tid + i * 256;
            int m = idx >> 4, c = idx & 15;
            As[m][c] = Aq[(size_t)(m0 + m) * DIM + c0 + c];
        }
        #pragma unroll
        for (int i = 0; i < 8; i++) {
            int idx = tid + i * 256;
            int j = idx >> 4, c = idx & 15;
            Bs[j][c] = Bk[(size_t)(j0 + j) * DIM + c0 + c];
        }
        __syncthreads();
        #pragma unroll
        for (int c = 0; c < 16; c++) {
            float ra[8], rb[8];
            #pragma unroll
            for (int i = 0; i < 8; i++) ra[i] = As[ty * 8 + i][c];
            #pragma unroll
            for (int j = 0; j < 8; j++) rb[j] = Bs[tx * 8 + j][c];
            #pragma unroll
            for (int i = 0; i < 8; i++)
                #pragma unroll
                for (int j = 0; j < 8; j++) acc[i][j] += ra[i] * rb[j];
        }
        __syncthreads();
    }
    float* Cp = attn + (size_t)z * NK * HW;
    #pragma unroll
    for (int i = 0; i < 8; i++)
        #pragma unroll
        for (int j = 0; j < 8; j++)
            Cp[(size_t)(m0 + ty * 8 + i) * HW + j0 + tx * 8 + j] = acc[i][j] * 0.125f;
}

// =================================================================
// Row softmax over 4096 (in place). One block / row, 16 elems / thread in regs.
// =================================================================
__global__ void softmax4096(float* __restrict__ attn) {
    __shared__ float red[8];
    float* p = attn + (size_t)blockIdx.x * 4096;
    const int t = threadIdx.x;
    float v[16];
    float mx = -3.4e38f;
    #pragma unroll
    for (int i = 0; i < 16; i++) { v[i] = p[t + i * 256]; mx = fmaxf(mx, v[i]); }
    #pragma unroll
    for (int o = 16; o; o >>= 1) mx = fmaxf(mx, __shfl_xor_sync(0xffffffffu, mx, o));
    if ((t & 31) == 0) red[t >> 5] = mx;
    __syncthreads();
    float m0 = red[0];
    #pragma unroll
    for (int i = 1; i < 8; i++) m0 = fmaxf(m0, red[i]);
    float s = 0.f;
    #pragma unroll
    for (int i = 0; i < 16; i++) { v[i] = __expf(v[i] - m0); s += v[i]; }
    #pragma unroll
    for (int o = 16; o; o >>= 1) s += __shfl_xor_sync(0xffffffffu, s, o);
    __syncthreads();
    if ((t & 31) == 0) red[t >> 5] = s;
    __syncthreads();
    float tot = 0.f;
    #pragma unroll
    for (int i = 0; i < 8; i++) tot += red[i];
    const float inv = 1.0f / tot;
    #pragma unroll
    for (int i = 0; i < 16; i++) p[t + i * 256] = v[i] * inv;
}

// =================================================================
// AV: per (b,h): O[k,dv] = sum_n attn[k,n] * V[n,dv]
// BM=128, BN=64, BK=32; grid (1, 2, 64). 8x4 microtile.
// =================================================================
__global__ void gemm_av(const float* __restrict__ attn, const float* __restrict__ gv,
                        float* __restrict__ gao) {
    __shared__ float As[128][33];
    __shared__ float Bs[32][65];
    const int tid = threadIdx.x;
    const int tx = tid & 15, ty = tid >> 4;
    const int z = blockIdx.z, b = z >> 3, h = z & 7;
    const int m0 = blockIdx.y * 128;
    const float* Ap = attn + (size_t)z * NK * HW;            // lda 4096
    const float* Bp = gv + (size_t)b * HW * DIM + h * HD;    // ldb 512
    float acc[8][4];
    #pragma unroll
    for (int i = 0; i < 8; i++)
        #pragma unroll
        for (int j = 0; j < 4; j++) acc[i][j] = 0.f;

    for (int c0 = 0; c0 < 4096; c0 += 32) {
        #pragma unroll
        for (int i = 0; i < 16; i++) {
            int idx = tid + i * 256;
            int m = idx >> 5, c = idx & 31;
            As[m][c] = Ap[(size_t)(m0 + m) * HW + c0 + c];
        }
        #pragma unroll
        for (int i = 0; i < 8; i++) {
            int idx = tid + i * 256;
            int c = idx >> 6, j = idx & 63;
            Bs[c][j] = Bp[(size_t)(c0 + c) * DIM + j];
        }
        __syncthreads();
        #pragma unroll
        for (int c = 0; c < 32; c++) {
            float ra[8], rb[4];
            #pragma unroll
            for (int i = 0; i < 8; i++) ra[i] = As[ty * 8 + i][c];
            #pragma unroll
            for (int j = 0; j < 4; j++) rb[j] = Bs[c][tx * 4 + j];
            #pragma unroll
            for (int i = 0; i < 8; i++)
                #pragma unroll
                for (int j = 0; j < 4; j++) acc[i][j] += ra[i] * rb[j];
        }
        __syncthreads();
    }
    float* Cp = gao + (size_t)b * NK * DIM + h * HD;
    #pragma unroll
    for (int i = 0; i < 8; i++)
        #pragma unroll
        for (int j = 0; j < 4; j++)
            Cp[(size_t)(m0 + ty * 8 + i) * DIM + tx * 4 + j] = acc[i][j];
}

// =================================================================
// LayerNorm over 512 per row. One block / row, 2 elems / thread.
// =================================================================
__global__ void ln_kernel(const float* __restrict__ x, const float* __restrict__ g,
                          const float* __restrict__ bb, float* __restrict__ out) {
    __shared__ float red[8];
    const int row = blockIdx.x, t = threadIdx.x;
    const float* xr = x + (size_t)row * 512;
    const float v0 = xr[t], v1 = xr[t + 256];
    float s = v0 + v1;
    #pragma unroll
    for (int o = 16; o; o >>= 1) s += __shfl_xor_sync(0xffffffffu, s, o);
    if ((t & 31) == 0) red[t >> 5] = s;
    __syncthreads();
    float tot = 0.f;
    #pragma unroll
    for (int i = 0; i < 8; i++) tot += red[i];
    const float mu = tot * (1.0f / 512.0f);
    const float d0 = v0 - mu, d1 = v1 - mu;
    float q = d0 * d0 + d1 * d1;
    __syncthreads();
    #pragma unroll
    for (int o = 16; o; o >>= 1) q += __shfl_xor_sync(0xffffffffu, q, o);
    if ((t & 31) == 0) red[t >> 5] = q;
    __syncthreads();
    tot = 0.f;
    #pragma unroll
    for (int i = 0; i < 8; i++) tot += red[i];
    const float inv = rsqrtf(tot * (1.0f / 512.0f) + 1e-5f);
    out[(size_t)row * 512 + t]       = d0 * inv * g[t] + bb[t];
    out[(size_t)row * 512 + t + 256] = d1 * inv * g[t + 256] + bb[t + 256];
}

// =================================================================
extern "C" void kernel_launch(void* const* d_in, const int* in_sizes, int n_in,
                              void* d_out, int out_size) {
    const float* hidden = (const float*)d_in[0];
    const float* aux    = (const float*)d_in[1];
    const float* Wq = (const float*)d_in[2];
    const float* bq = (const float*)d_in[3];
    const float* Wk = (const float*)d_in[4];
    const float* bk = (const float*)d_in[5];
    const float* Wv = (const float*)d_in[6];
    const float* bv = (const float*)d_in[7];
    const float* Wo = (const float*)d_in[8];
    const float* bo = (const float*)d_in[9];
    const float* lng = (const float*)d_in[10];
    const float* lnb = (const float*)d_in[11];
    float* out = (float*)d_out;

    float *gq, *gk, *gv, *gao, *gx;
    cudaGetSymbolAddress((void**)&gq,  g_q);
    cudaGetSymbolAddress((void**)&gk,  g_k);
    cudaGetSymbolAddress((void**)&gv,  g_v);
    cudaGetSymbolAddress((void**)&gao, g_ao);
    cudaGetSymbolAddress((void**)&gx,  g_x);

    const size_t AUXOUT = (size_t)2048 * 512;
    const size_t ATTN_N = (size_t)64 * 256 * 4096;
    float* attn;
    if ((size_t)out_size >= AUXOUT + ATTN_N) {
        attn = out + AUXOUT;                       // outputs concatenated: aux_out, attn
    } else {
        cudaGetSymbolAddress((void**)&attn, g_attn_fb);  // attn not part of output
    }

    dim3 blk(256);
    // Q projection: (2048 x 512 x 512)
    gemm128<false><<<dim3(4, 16), blk>>>(aux, Wq, bq, nullptr, gq);
    // K / V projections from hidden feature map: (32768 x 512 x 512) each
    gemm128<true ><<<dim3(4, 256), blk>>>(hidden, Wk, bk, nullptr, gk);
    gemm128<true ><<<dim3(4, 256), blk>>>(hidden, Wv, bv, nullptr, gv);
    // scores = scale * Q K^T  -> attn region
    gemm_nt_scores<<<dim3(32, 2, 64), blk>>>(gq, gk, attn);
    // softmax over keys (in place)
    softmax4096<<<16384, 256>>>(attn);
    // O = attn @ V
    gemm_av<<<dim3(1, 2, 64), blk>>>(attn, gv, gao);
    // out-proj + residual add
    gemm128<false><<<dim3(4, 16), blk>>>(gao, Wo, bo, aux, gx);
    // LayerNorm -> aux_out
    ln_kernel<<<2048, 256>>>(gx, lng, lnb, out);
}

// round 2
// speedup vs baseline: 2.8706x; 2.8706x over previous
#include <cuda_runtime.h>
#include <cstddef>

#define HW    4096
#define NK    256
#define DIM   512

// ---------------- scratch (no allocation allowed) ----------------
__device__ float g_q [2048u  * 512u];
__device__ float g_k [32768u * 512u];
__device__ float g_v [32768u * 512u];
__device__ float g_ao[2048u  * 512u];
__device__ float g_x [2048u  * 512u];
__device__ float g_attn_fb[(size_t)64 * 256 * 4096];  // fallback if attn not in d_out

// ---------------- tf32 helpers ----------------
__device__ __forceinline__ unsigned f2tf(float x) {
    unsigned r;
    asm("cvt.rna.tf32.f32 %0, %1;" : "=r"(r) : "f"(x));
    return r;
}

__device__ __forceinline__ void mma_tf32(float* c, const unsigned* a, const unsigned* b) {
    asm volatile(
        "mma.sync.aligned.m16n8k8.row.col.f32.tf32.tf32.f32 "
        "{%0,%1,%2,%3}, {%4,%5,%6,%7}, {%8,%9}, {%0,%1,%2,%3};\n"
        : "+f"(c[0]), "+f"(c[1]), "+f"(c[2]), "+f"(c[3])
        : "r"(a[0]), "r"(a[1]), "r"(a[2]), "r"(a[3]), "r"(b[0]), "r"(b[1]));
}

// =================================================================
// Generic 128x128 tf32 tensor-core GEMM. 256 threads = 8 warps (2m x 4n),
// warp tile 64x32, BK=32.
//   HID_A : A element (m = b*4096+n, c) comes from hid[b][c][n] (b=m0>>12)
//   BT    : B given as [N][K] row-major (NT GEMM); else B is [K][N] (NN)
//   HEADS : batched-by-(b,h): z = b*8+h; A += b*sAz + h*64; B += b*sBz + h*64;
//           C += z*sCz
// Smem stride 36 words -> fragment LDS bank (4m+k)%32: conflict-free.
// =================================================================
template<bool HID_A, bool BT, bool HEADS>
__global__ __launch_bounds__(256, 2)
void gemm128_tf32(const float* __restrict__ A, const float* __restrict__ B,
                  const float* __restrict__ bias, const float* __restrict__ resid,
                  float* __restrict__ C,
                  int lda, int ldb, int ldc, int Ksize,
                  long sAz, long sBz, long sCz, float scale)
{
    __shared__ unsigned As[128][36];
    __shared__ unsigned Bs[128][36];
    const int tid = threadIdx.x;
    if (HEADS) {
        const int z = blockIdx.z, b = z >> 3, h = z & 7;
        A += (size_t)b * sAz + h * 64;
        B += (size_t)b * sBz + h * 64;
        C += (size_t)z * sCz;
    }
    const int m0 = blockIdx.y * 128, j0 = blockIdx.x * 128;
    const int w = tid >> 5, lane = tid & 31, g = lane >> 2, tig = lane & 3;
    const int mw = (w >> 2) * 64, nw = (w & 3) * 32;

    float acc[4][4][4];
    #pragma unroll
    for (int i = 0; i < 4; i++)
        #pragma unroll
        for (int j = 0; j < 4; j++)
            #pragma unroll
            for (int r = 0; r < 4; r++) acc[i][j][r] = 0.f;

    for (int c0 = 0; c0 < Ksize; c0 += 32) {
        // ---- load A tile (128 x 32) ----
        #pragma unroll
        for (int i = 0; i < 16; i++) {
            int idx = tid + i * 256;
            if (HID_A) {
                int kk = idx >> 7, m = idx & 127;     // m fastest: coalesced over n
                int bb = m0 >> 12, n0 = m0 & 4095;
                As[m][kk] = f2tf(A[((size_t)bb * DIM + c0 + kk) * HW + n0 + m]);
            } else {
                int m = idx >> 5, kk = idx & 31;      // kk fastest: coalesced in row
                As[m][kk] = f2tf(A[(size_t)(m0 + m) * lda + c0 + kk]);
            }
        }
        // ---- load B tile into Bs[n][k] ----
        #pragma unroll
        for (int i = 0; i < 16; i++) {
            int idx = tid + i * 256;
            if (BT) {
                int n = idx >> 5, kk = idx & 31;      // kk fastest
                Bs[n][kk] = f2tf(B[(size_t)(j0 + n) * ldb + c0 + kk]);
            } else {
                int kk = idx >> 7, n = idx & 127;     // n fastest
                Bs[n][kk] = f2tf(B[(size_t)(c0 + kk) * ldb + j0 + n]);
            }
        }
        __syncthreads();
        #pragma unroll
        for (int k8 = 0; k8 < 4; k8++) {
            unsigned af[4][4], bf[4][2];
            const int kb = k8 * 8 + tig;
            #pragma unroll
            for (int im = 0; im < 4; im++) {
                int r = mw + im * 16 + g;
                af[im][0] = As[r][kb];
                af[im][1] = As[r + 8][kb];
                af[im][2] = As[r][kb + 4];
                af[im][3] = As[r + 8][kb + 4];
            }
            #pragma unroll
            for (int jn = 0; jn < 4; jn++) {
                int n = nw + jn * 8 + g;
                bf[jn][0] = Bs[n][kb];
                bf[jn][1] = Bs[n][kb + 4];
            }
            #pragma unroll
            for (int im = 0; im < 4; im++)
                #pragma unroll
                for (int jn = 0; jn < 4; jn++)
                    mma_tf32(acc[im][jn], af[im], bf[jn]);
        }
        __syncthreads();
    }
    // ---- epilogue ----
    #pragma unroll
    for (int im = 0; im < 4; im++) {
        #pragma unroll
        for (int jn = 0; jn < 4; jn++) {
            const int r0 = m0 + mw + im * 16 + g;
            const int col = j0 + nw + jn * 8 + 2 * tig;
            const float* cc = acc[im][jn];
            #pragma unroll
            for (int half = 0; half < 2; half++) {
                const int r = r0 + half * 8;
                #pragma unroll
                for (int cix = 0; cix < 2; cix++) {
                    float v = cc[half * 2 + cix] * scale;
                    const int jj = col + cix;
                    if (bias)  v += bias[jj];
                    if (resid) v += resid[(size_t)r * ldc + jj];
                    C[(size_t)r * ldc + jj] = v;
                }
            }
        }
    }
}

// =================================================================
// AV: per (b,h): O[k,dv] = sum_n attn[k,n] * V[n,dv]. 64x64 block,
// 8 warps (4m x 2n), warp tile 16x32, BK=32, K=4096.
// =================================================================
__global__ __launch_bounds__(256, 4)
void gemm_av_tf32(const float* __restrict__ attn, const float* __restrict__ gv,
                  float* __restrict__ gao)
{
    __shared__ unsigned As[64][36];
    __shared__ unsigned Bs[64][36];
    const int tid = threadIdx.x;
    const int z = blockIdx.z, b = z >> 3, h = z & 7;
    const int m0 = blockIdx.y * 64;
    const int w = tid >> 5, lane = tid & 31, g = lane >> 2, tig = lane & 3;
    const int mw = (w >> 1) * 16, nw = (w & 1) * 32;
    const float* Ap = attn + (size_t)z * NK * HW;             // lda 4096
    const float* Bp = gv + (size_t)b * HW * DIM + h * 64;     // ldb 512

    float acc[4][4];
    #pragma unroll
    for (int j = 0; j < 4; j++)
        #pragma unroll
        for (int r = 0; r < 4; r++) acc[j][r] = 0.f;

    for (int c0 = 0; c0 < HW; c0 += 32) {
        #pragma unroll
        for (int i = 0; i < 8; i++) {
            int idx = tid + i * 256;
            int m = idx >> 5, kk = idx & 31;
            As[m][kk] = f2tf(Ap[(size_t)(m0 + m) * HW + c0 + kk]);
        }
        #pragma unroll
        for (int i = 0; i < 8; i++) {
            int idx = tid + i * 256;
            int n = idx & 63, kk = idx >> 6;
            Bs[n][kk] = f2tf(Bp[(size_t)(c0 + kk) * DIM + n]);
        }
        __syncthreads();
        #pragma unroll
        for (int k8 = 0; k8 < 4; k8++) {
            const int kb = k8 * 8 + tig;
            unsigned af[4], bf[4][2];
            {
                int r = mw + g;
                af[0] = As[r][kb];
                af[1] = As[r + 8][kb];
                af[2] = As[r][kb + 4];
                af[3] = As[r + 8][kb + 4];
            }
            #pragma unroll
            for (int jn = 0; jn < 4; jn++) {
                int n = nw + jn * 8 + g;
                bf[jn][0] = Bs[n][kb];
                bf[jn][1] = Bs[n][kb + 4];
            }
            #pragma unroll
            for (int jn = 0; jn < 4; jn++)
                mma_tf32(acc[jn], af, bf[jn]);
        }
        __syncthreads();
    }
    float* Cp = gao + (size_t)b * NK * DIM + h * 64;
    #pragma unroll
    for (int jn = 0; jn < 4; jn++) {
        const int r0 = m0 + mw + g;
        const int col = nw + jn * 8 + 2 * tig;
        #pragma unroll
        for (int half = 0; half < 2; half++) {
            const int r = r0 + half * 8;
            Cp[(size_t)r * DIM + col]     = acc[jn][half * 2];
            Cp[(size_t)r * DIM + col + 1] = acc[jn][half * 2 + 1];
        }
    }
}

// =================================================================
// Row softmax over 4096 (in place). One block / row, 16 elems / thread.
// =================================================================
__global__ void softmax4096(float* __restrict__ attn) {
    __shared__ float red[8];
    float* p = attn + (size_t)blockIdx.x * 4096;
    const int t = threadIdx.x;
    float v[16];
    float mx = -3.4e38f;
    #pragma unroll
    for (int i = 0; i < 16; i++) { v[i] = p[t + i * 256]; mx = fmaxf(mx, v[i]); }
    #pragma unroll
    for (int o = 16; o; o >>= 1) mx = fmaxf(mx, __shfl_xor_sync(0xffffffffu, mx, o));
    if ((t & 31) == 0) red[t >> 5] = mx;
    __syncthreads();
    float m0 = red[0];
    #pragma unroll
    for (int i = 1; i < 8; i++) m0 = fmaxf(m0, red[i]);
    float s = 0.f;
    #pragma unroll
    for (int i = 0; i < 16; i++) { v[i] = __expf(v[i] - m0); s += v[i]; }
    #pragma unroll
    for (int o = 16; o; o >>= 1) s += __shfl_xor_sync(0xffffffffu, s, o);
    __syncthreads();
    if ((t & 31) == 0) red[t >> 5] = s;
    __syncthreads();
    float tot = 0.f;
    #pragma unroll
    for (int i = 0; i < 8; i++) tot += red[i];
    const float inv = 1.0f / tot;
    #pragma unroll
    for (int i = 0; i < 16; i++) p[t + i * 256] = v[i] * inv;
}

// =================================================================
// LayerNorm over 512 per row. One block / row, 2 elems / thread.
// =================================================================
__global__ void ln_kernel(const float* __restrict__ x, const float* __restrict__ g,
                          const float* __restrict__ bb, float* __restrict__ out) {
    __shared__ float red[8];
    const int row = blockIdx.x, t = threadIdx.x;
    const float* xr = x + (size_t)row * 512;
    const float v0 = xr[t], v1 = xr[t + 256];
    float s = v0 + v1;
    #pragma unroll
    for (int o = 16; o; o >>= 1) s += __shfl_xor_sync(0xffffffffu, s, o);
    if ((t & 31) == 0) red[t >> 5] = s;
    __syncthreads();
    float tot = 0.f;
    #pragma unroll
    for (int i = 0; i < 8; i++) tot += red[i];
    const float mu = tot * (1.0f / 512.0f);
    const float d0 = v0 - mu, d1 = v1 - mu;
    float q = d0 * d0 + d1 * d1;
    __syncthreads();
    #pragma unroll
    for (int o = 16; o; o >>= 1) q += __shfl_xor_sync(0xffffffffu, q, o);
    if ((t & 31) == 0) red[t >> 5] = q;
    __syncthreads();
    tot = 0.f;
    #pragma unroll
    for (int i = 0; i < 8; i++) tot += red[i];
    const float inv = rsqrtf(tot * (1.0f / 512.0f) + 1e-5f);
    out[(size_t)row * 512 + t]       = d0 * inv * g[t] + bb[t];
    out[(size_t)row * 512 + t + 256] = d1 * inv * g[t + 256] + bb[t + 256];
}

// =================================================================
extern "C" void kernel_launch(void* const* d_in, const int* in_sizes, int n_in,
                              void* d_out, int out_size) {
    const float* hidden = (const float*)d_in[0];
    const float* aux    = (const float*)d_in[1];
    const float* Wq = (const float*)d_in[2];
    const float* bq = (const float*)d_in[3];
    const float* Wk = (const float*)d_in[4];
    const float* bk = (const float*)d_in[5];
    const float* Wv = (const float*)d_in[6];
    const float* bv = (const float*)d_in[7];
    const float* Wo = (const float*)d_in[8];
    const float* bo = (const float*)d_in[9];
    const float* lng = (const float*)d_in[10];
    const float* lnb = (const float*)d_in[11];
    float* out = (float*)d_out;

    float *gq, *gk, *gv, *gao, *gx;
    cudaGetSymbolAddress((void**)&gq,  g_q);
    cudaGetSymbolAddress((void**)&gk,  g_k);
    cudaGetSymbolAddress((void**)&gv,  g_v);
    cudaGetSymbolAddress((void**)&gao, g_ao);
    cudaGetSymbolAddress((void**)&gx,  g_x);

    const size_t AUXOUT = (size_t)2048 * 512;
    const size_t ATTN_N = (size_t)64 * 256 * 4096;
    float* attn;
    if ((size_t)out_size >= AUXOUT + ATTN_N) {
        attn = out + AUXOUT;                       // outputs concatenated: aux_out, attn
    } else {
        cudaGetSymbolAddress((void**)&attn, g_attn_fb);
    }

    dim3 blk(256);
    // Q projection: 2048 x 512 x 512
    gemm128_tf32<false, false, false><<<dim3(4, 16, 1), blk>>>(
        aux, Wq, bq, nullptr, gq, 512, 512, 512, 512, 0, 0, 0, 1.f);
    // K / V projections: 32768 x 512 x 512 (A from hidden feature map)
    gemm128_tf32<true, false, false><<<dim3(4, 256, 1), blk>>>(
        hidden, Wk, bk, nullptr, gk, 512, 512, 512, 512, 0, 0, 0, 1.f);
    gemm128_tf32<true, false, false><<<dim3(4, 256, 1), blk>>>(
        hidden, Wv, bv, nullptr, gv, 512, 512, 512, 512, 0, 0, 0, 1.f);
    // scores = 0.125 * Q K^T  (batched over 64 (b,h), NT, K=64)
    gemm128_tf32<false, true, true><<<dim3(32, 2, 64), blk>>>(
        gq, gk, nullptr, nullptr, attn, 512, 512, 4096, 64,
        (long)NK * DIM, (long)HW * DIM, (long)NK * HW, 0.125f);
    // softmax over keys (in place)
    softmax4096<<<16384, 256>>>(attn);
    // O = attn @ V
    gemm_av_tf32<<<dim3(1, 4, 64), blk>>>(attn, gv, gao);
    // out-proj + residual
    gemm128_tf32<false, false, false><<<dim3(4, 16, 1), blk>>>(
        gao, Wo, bo, aux, gx, 512, 512, 512, 512, 0, 0, 0, 1.f);
    // LayerNorm
    ln_kernel<<<2048, 256>>>(gx, lng, lnb, out);
}

// round 3
// speedup vs baseline: 5.4471x; 1.8976x over previous
#include <cuda_runtime.h>
#include <cstddef>

#define HW    4096
#define NK    256
#define DIM   512

// ---------------- scratch (no allocation allowed) ----------------
__device__ float g_q [2048u  * 512u];
__device__ float g_k [32768u * 512u];
__device__ float g_v [32768u * 512u];
__device__ float g_ao[2048u  * 512u];
__device__ float g_x [2048u  * 512u];
__device__ float g_attn_fb[(size_t)64 * 256 * 4096];  // fallback if attn not in d_out

// ---------------- helpers ----------------
__device__ __forceinline__ unsigned f2tf(float x) {
    unsigned r;
    asm("cvt.rna.tf32.f32 %0, %1;" : "=r"(r) : "f"(x));
    return r;
}
__device__ __forceinline__ void mma_tf32(float* c, const unsigned* a, const unsigned* b) {
    asm volatile(
        "mma.sync.aligned.m16n8k8.row.col.f32.tf32.tf32.f32 "
        "{%0,%1,%2,%3}, {%4,%5,%6,%7}, {%8,%9}, {%0,%1,%2,%3};\n"
        : "+f"(c[0]), "+f"(c[1]), "+f"(c[2]), "+f"(c[3])
        : "r"(a[0]), "r"(a[1]), "r"(a[2]), "r"(a[3]), "r"(b[0]), "r"(b[1]));
}
__device__ __forceinline__ void cp16(float* dst, const float* src) {
    unsigned d = (unsigned)__cvta_generic_to_shared(dst);
    asm volatile("cp.async.cg.shared.global [%0], [%1], 16;" :: "r"(d), "l"(src));
}
__device__ __forceinline__ void cpcommit() { asm volatile("cp.async.commit_group;"); }
template<int N> __device__ __forceinline__ void cpwait() {
    asm volatile("cp.async.wait_group %0;" :: "n"(N));
}

// =================================================================
// Projection GEMM: C[M,512] = A[M,512] @ W[512,512] (+bias)(+resid)
// 128x128 tile, BK=32, 8 warps (2m x 4n), warp tile 64x32.
// cp.async double-buffered; smem holds raw fp32; tf32 convert at frag load.
// HID_A: A element (m = b*4096+n, c) = hid[b][c][n]
// =================================================================
template<bool HID_A>
__global__ __launch_bounds__(256, 2)
void gemm128ca(const float* __restrict__ A, const float* __restrict__ W,
               const float* __restrict__ bias, const float* __restrict__ resid,
               float* __restrict__ C)
{
    extern __shared__ float sm[];
    // non-HID: As [2][128][36] then Bs [2][32][136]
    // HID    : AsT [2][32][136] then Bs [2][32][136]
    float* Abase = sm;
    float* Bbase = sm + (HID_A ? 2 * 32 * 136 : 2 * 128 * 36);

    const int tid = threadIdx.x;
    const int m0 = blockIdx.y * 128, j0 = blockIdx.x * 128;
    const int w = tid >> 5, lane = tid & 31, g = lane >> 2, tig = lane & 3;
    const int mw = (w >> 2) * 64, nw = (w & 3) * 32;

    auto loadA = [&](int buf, int c0) {
        if (HID_A) {
            float* dst = Abase + buf * 32 * 136;
            const int bb = m0 >> 12, n0 = m0 & 4095;
            #pragma unroll
            for (int i = 0; i < 4; i++) {
                int id = tid + i * 256;
                int k = id >> 5, m4 = (id & 31) * 4;
                cp16(dst + k * 136 + m4,
                     A + ((size_t)(bb * 512 + c0 + k)) * 4096 + n0 + m4);
            }
        } else {
            float* dst = Abase + buf * 128 * 36;
            #pragma unroll
            for (int i = 0; i < 4; i++) {
                int id = tid + i * 256;
                int m = id >> 3, c4 = (id & 7) * 4;
                cp16(dst + m * 36 + c4, A + (size_t)(m0 + m) * 512 + c0 + c4);
            }
        }
    };
    auto loadB = [&](int buf, int c0) {
        float* dst = Bbase + buf * 32 * 136;
        #pragma unroll
        for (int i = 0; i < 4; i++) {
            int id = tid + i * 256;
            int k = id >> 5, n4 = (id & 31) * 4;
            cp16(dst + k * 136 + n4, W + (size_t)(c0 + k) * 512 + j0 + n4);
        }
    };

    float acc[4][4][4];
    #pragma unroll
    for (int i = 0; i < 4; i++)
        #pragma unroll
        for (int j = 0; j < 4; j++)
            #pragma unroll
            for (int r = 0; r < 4; r++) acc[i][j][r] = 0.f;

    loadA(0, 0); loadB(0, 0); cpcommit();
    for (int t = 0; t < 16; t++) {
        const int buf = t & 1;
        if (t < 15) { loadA(buf ^ 1, (t + 1) * 32); loadB(buf ^ 1, (t + 1) * 32); cpcommit(); cpwait<1>(); }
        else cpwait<0>();
        __syncthreads();
        const float* As = HID_A ? (Abase + buf * 32 * 136) : (Abase + buf * 128 * 36);
        const float* Bs = Bbase + buf * 32 * 136;
        #pragma unroll
        for (int k8 = 0; k8 < 4; k8++) {
            const int kb = k8 * 8 + tig;
            unsigned af[4][4], bf[4][2];
            #pragma unroll
            for (int im = 0; im < 4; im++) {
                const int r = mw + im * 16 + g;
                if (HID_A) {
                    af[im][0] = f2tf(As[kb * 136 + r]);
                    af[im][1] = f2tf(As[kb * 136 + r + 8]);
                    af[im][2] = f2tf(As[(kb + 4) * 136 + r]);
                    af[im][3] = f2tf(As[(kb + 4) * 136 + r + 8]);
                } else {
                    af[im][0] = f2tf(As[r * 36 + kb]);
                    af[im][1] = f2tf(As[(r + 8) * 36 + kb]);
                    af[im][2] = f2tf(As[r * 36 + kb + 4]);
                    af[im][3] = f2tf(As[(r + 8) * 36 + kb + 4]);
                }
            }
            #pragma unroll
            for (int jn = 0; jn < 4; jn++) {
                const int n = nw + jn * 8 + g;
                bf[jn][0] = f2tf(Bs[kb * 136 + n]);
                bf[jn][1] = f2tf(Bs[(kb + 4) * 136 + n]);
            }
            #pragma unroll
            for (int im = 0; im < 4; im++)
                #pragma unroll
                for (int jn = 0; jn < 4; jn++)
                    mma_tf32(acc[im][jn], af[im], bf[jn]);
        }
        __syncthreads();
    }
    // epilogue
    #pragma unroll
    for (int im = 0; im < 4; im++) {
        #pragma unroll
        for (int jn = 0; jn < 4; jn++) {
            const int r0 = m0 + mw + im * 16 + g;
            const int col = j0 + nw + jn * 8 + 2 * tig;
            const float* cc = acc[im][jn];
            #pragma unroll
            for (int half = 0; half < 2; half++) {
                const int r = r0 + half * 8;
                float v0 = cc[half * 2]     + bias[col];
                float v1 = cc[half * 2 + 1] + bias[col + 1];
                if (resid) {
                    v0 += resid[(size_t)r * 512 + col];
                    v1 += resid[(size_t)r * 512 + col + 1];
                }
                *(float2*)(C + (size_t)r * 512 + col) = make_float2(v0, v1);
            }
        }
    }
}

// =================================================================
// Fused attention: per (b,h, 64-query tile):
//   pass1: stream K tiles (64 keys), S = 0.125*Q K^T, online row max/sum
//   pass2: recompute S, P = exp(S-m)/l -> write attn (fp32) + smem,
//          O += P @ V (tf32 mma). cp.async double-buffered K/V.
// block = 128 thr (4 warps x 16 query rows), grid = (4, 64)
// =================================================================
__device__ __forceinline__ void mma_S(float s[8][4], const float* Kbuf,
                                      const unsigned qf[8][4], int g, int tig) {
    #pragma unroll
    for (int jn = 0; jn < 8; jn++) { s[jn][0] = s[jn][1] = s[jn][2] = s[jn][3] = 0.f; }
    #pragma unroll
    for (int ks = 0; ks < 8; ks++) {
        const int kb = ks * 8 + tig;
        #pragma unroll
        for (int jn = 0; jn < 8; jn++) {
            unsigned bf[2];
            bf[0] = f2tf(Kbuf[(jn * 8 + g) * 68 + kb]);
            bf[1] = f2tf(Kbuf[(jn * 8 + g) * 68 + kb + 4]);
            mma_tf32(s[jn], qf[ks], bf);
        }
    }
}

__global__ __launch_bounds__(128, 2)
void flash_attn(const float* __restrict__ gq, const float* __restrict__ gk,
                const float* __restrict__ gv, float* __restrict__ attn,
                float* __restrict__ gao)
{
    extern __shared__ float sm[];
    float* Ks = sm;                          // [2][64][68]
    float* Vs = sm + 2 * 64 * 68;            // [2][64][72]
    float* Ps = sm + 2 * 64 * 68 + 2 * 64 * 72;  // [4 warps][16][68]

    const int tid = threadIdx.x;
    const int w = tid >> 5, lane = tid & 31, g = lane >> 2, tig = lane & 3;
    const int z = blockIdx.y, b = z >> 3, h = z & 7;
    const int m0 = blockIdx.x * 64;
    const float* Qp = gq + ((size_t)(b * 256 + m0)) * 512 + h * 64;
    const float* Kp = gk + (size_t)b * HW * 512 + h * 64;
    const float* Vp = gv + (size_t)b * HW * 512 + h * 64;
    float* Ap = attn + (size_t)z * NK * HW + (size_t)m0 * HW;
    float* Op = gao + ((size_t)(b * 256 + m0)) * 512 + h * 64;

    const int r0 = w * 16 + g;

    // Q fragments (scale 1/sqrt(64) folded in)
    unsigned qf[8][4];
    #pragma unroll
    for (int ks = 0; ks < 8; ks++) {
        qf[ks][0] = f2tf(0.125f * Qp[(size_t)r0 * 512 + ks * 8 + tig]);
        qf[ks][1] = f2tf(0.125f * Qp[(size_t)(r0 + 8) * 512 + ks * 8 + tig]);
        qf[ks][2] = f2tf(0.125f * Qp[(size_t)r0 * 512 + ks * 8 + tig + 4]);
        qf[ks][3] = f2tf(0.125f * Qp[(size_t)(r0 + 8) * 512 + ks * 8 + tig + 4]);
    }

    auto loadK = [&](int buf, int kt) {
        float* dst = Ks + buf * 64 * 68;
        const float* src = Kp + (size_t)kt * 64 * 512;
        #pragma unroll
        for (int i = 0; i < 8; i++) {
            int id = tid + i * 128;
            int row = id >> 4, c4 = (id & 15) * 4;
            cp16(dst + row * 68 + c4, src + (size_t)row * 512 + c4);
        }
    };
    auto loadV = [&](int buf, int kt) {
        float* dst = Vs + buf * 64 * 72;
        const float* src = Vp + (size_t)kt * 64 * 512;
        #pragma unroll
        for (int i = 0; i < 8; i++) {
            int id = tid + i * 128;
            int row = id >> 4, c4 = (id & 15) * 4;
            cp16(dst + row * 72 + c4, src + (size_t)row * 512 + c4);
        }
    };

    float m[2] = {-1e30f, -1e30f}, l[2] = {0.f, 0.f};

    // ---- pass 1: row max / sum ----
    loadK(0, 0); cpcommit();
    for (int kt = 0; kt < 64; kt++) {
        const int buf = kt & 1;
        if (kt < 63) { loadK(buf ^ 1, kt + 1); cpcommit(); cpwait<1>(); }
        else cpwait<0>();
        __syncthreads();
        float s[8][4];
        mma_S(s, Ks + buf * 64 * 68, qf, g, tig);
        #pragma unroll
        for (int rr = 0; rr < 2; rr++) {
            float mx = -1e30f;
            #pragma unroll
            for (int jn = 0; jn < 8; jn++)
                mx = fmaxf(mx, fmaxf(s[jn][2 * rr], s[jn][2 * rr + 1]));
            mx = fmaxf(mx, __shfl_xor_sync(0xffffffffu, mx, 1));
            mx = fmaxf(mx, __shfl_xor_sync(0xffffffffu, mx, 2));
            const float mn = fmaxf(m[rr], mx);
            float sum = 0.f;
            #pragma unroll
            for (int jn = 0; jn < 8; jn++)
                sum += __expf(s[jn][2 * rr] - mn) + __expf(s[jn][2 * rr + 1] - mn);
            sum += __shfl_xor_sync(0xffffffffu, sum, 1);
            sum += __shfl_xor_sync(0xffffffffu, sum, 2);
            l[rr] = l[rr] * __expf(m[rr] - mn) + sum;
            m[rr] = mn;
        }
        __syncthreads();
    }
    const float invl0 = 1.f / l[0], invl1 = 1.f / l[1];

    // ---- pass 2: P writes + O accumulation ----
    float o[8][4];
    #pragma unroll
    for (int jn = 0; jn < 8; jn++)
        #pragma unroll
        for (int r = 0; r < 4; r++) o[jn][r] = 0.f;

    loadK(0, 0); loadV(0, 0); cpcommit();
    float* Pw = Ps + w * 16 * 68;
    for (int kt = 0; kt < 64; kt++) {
        const int buf = kt & 1;
        if (kt < 63) { loadK(buf ^ 1, kt + 1); loadV(buf ^ 1, kt + 1); cpcommit(); cpwait<1>(); }
        else cpwait<0>();
        __syncthreads();
        float s[8][4];
        mma_S(s, Ks + buf * 64 * 68, qf, g, tig);
        #pragma unroll
        for (int jn = 0; jn < 8; jn++) {
            const float p0 = __expf(s[jn][0] - m[0]) * invl0;
            const float p1 = __expf(s[jn][1] - m[0]) * invl0;
            const float p2 = __expf(s[jn][2] - m[1]) * invl1;
            const float p3 = __expf(s[jn][3] - m[1]) * invl1;
            const int col = jn * 8 + 2 * tig;
            *(float2*)(Ap + (size_t)r0 * HW + kt * 64 + col)       = make_float2(p0, p1);
            *(float2*)(Ap + (size_t)(r0 + 8) * HW + kt * 64 + col) = make_float2(p2, p3);
            *(float2*)(Pw + g * 68 + col)       = make_float2(p0, p1);
            *(float2*)(Pw + (g + 8) * 68 + col) = make_float2(p2, p3);
        }
        __syncwarp();
        const float* Vb = Vs + buf * 64 * 72;
        #pragma unroll
        for (int ks = 0; ks < 8; ks++) {
            const int kb = ks * 8 + tig;
            unsigned af[4];
            af[0] = f2tf(Pw[g * 68 + kb]);
            af[1] = f2tf(Pw[(g + 8) * 68 + kb]);
            af[2] = f2tf(Pw[g * 68 + kb + 4]);
            af[3] = f2tf(Pw[(g + 8) * 68 + kb + 4]);
            #pragma unroll
            for (int jn = 0; jn < 8; jn++) {
                const int n = jn * 8 + g;
                unsigned bf[2];
                bf[0] = f2tf(Vb[kb * 72 + n]);
                bf[1] = f2tf(Vb[(kb + 4) * 72 + n]);
                mma_tf32(o[jn], af, bf);
            }
        }
        __syncthreads();
    }
    // epilogue
    #pragma unroll
    for (int jn = 0; jn < 8; jn++) {
        const int col = jn * 8 + 2 * tig;
        *(float2*)(Op + (size_t)r0 * 512 + col)       = make_float2(o[jn][0], o[jn][1]);
        *(float2*)(Op + (size_t)(r0 + 8) * 512 + col) = make_float2(o[jn][2], o[jn][3]);
    }
}

// =================================================================
// LayerNorm over 512 per row.
// =================================================================
__global__ void ln_kernel(const float* __restrict__ x, const float* __restrict__ g,
                          const float* __restrict__ bb, float* __restrict__ out) {
    __shared__ float red[8];
    const int row = blockIdx.x, t = threadIdx.x;
    const float* xr = x + (size_t)row * 512;
    const float v0 = xr[t], v1 = xr[t + 256];
    float s = v0 + v1;
    #pragma unroll
    for (int o = 16; o; o >>= 1) s += __shfl_xor_sync(0xffffffffu, s, o);
    if ((t & 31) == 0) red[t >> 5] = s;
    __syncthreads();
    float tot = 0.f;
    #pragma unroll
    for (int i = 0; i < 8; i++) tot += red[i];
    const float mu = tot * (1.0f / 512.0f);
    const float d0 = v0 - mu, d1 = v1 - mu;
    float q = d0 * d0 + d1 * d1;
    __syncthreads();
    #pragma unroll
    for (int o = 16; o; o >>= 1) q += __shfl_xor_sync(0xffffffffu, q, o);
    if ((t & 31) == 0) red[t >> 5] = q;
    __syncthreads();
    tot = 0.f;
    #pragma unroll
    for (int i = 0; i < 8; i++) tot += red[i];
    const float inv = rsqrtf(tot * (1.0f / 512.0f) + 1e-5f);
    out[(size_t)row * 512 + t]       = d0 * inv * g[t] + bb[t];
    out[(size_t)row * 512 + t + 256] = d1 * inv * g[t + 256] + bb[t + 256];
}

// =================================================================
static const int SMEM_PROJ_N = (2 * 128 * 36 + 2 * 32 * 136) * 4;  // 71680
static const int SMEM_PROJ_H = (2 * 32 * 136 + 2 * 32 * 136) * 4;  // 69632
static const int SMEM_FLASH  = (2 * 64 * 68 + 2 * 64 * 72 + 4 * 16 * 68) * 4;  // 89088

extern "C" void kernel_launch(void* const* d_in, const int* in_sizes, int n_in,
                              void* d_out, int out_size) {
    const float* hidden = (const float*)d_in[0];
    const float* aux    = (const float*)d_in[1];
    const float* Wq = (const float*)d_in[2];
    const float* bq = (const float*)d_in[3];
    const float* Wk = (const float*)d_in[4];
    const float* bk = (const float*)d_in[5];
    const float* Wv = (const float*)d_in[6];
    const float* bv = (const float*)d_in[7];
    const float* Wo = (const float*)d_in[8];
    const float* bo = (const float*)d_in[9];
    const float* lng = (const float*)d_in[10];
    const float* lnb = (const float*)d_in[11];
    float* out = (float*)d_out;

    float *gq, *gk, *gv, *gao, *gx;
    cudaGetSymbolAddress((void**)&gq,  g_q);
    cudaGetSymbolAddress((void**)&gk,  g_k);
    cudaGetSymbolAddress((void**)&gv,  g_v);
    cudaGetSymbolAddress((void**)&gao, g_ao);
    cudaGetSymbolAddress((void**)&gx,  g_x);

    const size_t AUXOUT = (size_t)2048 * 512;
    const size_t ATTN_N = (size_t)64 * 256 * 4096;
    float* attn;
    if ((size_t)out_size >= AUXOUT + ATTN_N) {
        attn = out + AUXOUT;
    } else {
        cudaGetSymbolAddress((void**)&attn, g_attn_fb);
    }

    static bool attrs_set = false;
    if (!attrs_set) {
        cudaFuncSetAttribute(gemm128ca<false>, cudaFuncAttributeMaxDynamicSharedMemorySize, SMEM_PROJ_N);
        cudaFuncSetAttribute(gemm128ca<true>,  cudaFuncAttributeMaxDynamicSharedMemorySize, SMEM_PROJ_H);
        cudaFuncSetAttribute(flash_attn,       cudaFuncAttributeMaxDynamicSharedMemorySize, SMEM_FLASH);
        attrs_set = true;
    }

    // Q projection: 2048 x 512 x 512
    gemm128ca<false><<<dim3(4, 16), 256, SMEM_PROJ_N>>>(aux, Wq, bq, nullptr, gq);
    // K / V projections: 32768 x 512 x 512
    gemm128ca<true><<<dim3(4, 256), 256, SMEM_PROJ_H>>>(hidden, Wk, bk, nullptr, gk);
    gemm128ca<true><<<dim3(4, 256), 256, SMEM_PROJ_H>>>(hidden, Wv, bv, nullptr, gv);
    // fused scores + softmax + AV (+ attn output)
    flash_attn<<<dim3(4, 64), 128, SMEM_FLASH>>>(gq, gk, gv, attn, gao);
    // out-proj + residual
    gemm128ca<false><<<dim3(4, 16), 256, SMEM_PROJ_N>>>(gao, Wo, bo, aux, gx);
    // LayerNorm
    ln_kernel<<<2048, 256>>>(gx, lng, lnb, out);
}

// round 4
// speedup vs baseline: 5.7461x; 1.0549x over previous
#include <cuda_runtime.h>
#include <cstddef>

#define HW    4096
#define NK    256
#define DIM   512

// ---------------- scratch (no allocation allowed) ----------------
__device__ float g_q [2048u  * 512u];
__device__ float g_k [32768u * 512u];   // tf32-rounded bits
__device__ float g_v [32768u * 512u];   // tf32-rounded bits
__device__ float g_ao [2048u * 512u];
__device__ float g_aop[2u * 2048u * 512u];   // partial O per key-half
__device__ float g_x [2048u  * 512u];
__device__ float g_ml[64u * 4u * 2u * 64u * 2u];  // (z,qtile,half,row,{m,l})
__device__ float g_attn_fb[(size_t)64 * 256 * 4096];

// ---------------- helpers ----------------
__device__ __forceinline__ unsigned f2tf(float x) {
    unsigned r;
    asm("cvt.rna.tf32.f32 %0, %1;" : "=r"(r) : "f"(x));
    return r;
}
__device__ __forceinline__ void mma_tf32(float* c, const unsigned* a, const unsigned* b) {
    asm volatile(
        "mma.sync.aligned.m16n8k8.row.col.f32.tf32.tf32.f32 "
        "{%0,%1,%2,%3}, {%4,%5,%6,%7}, {%8,%9}, {%0,%1,%2,%3};\n"
        : "+f"(c[0]), "+f"(c[1]), "+f"(c[2]), "+f"(c[3])
        : "r"(a[0]), "r"(a[1]), "r"(a[2]), "r"(a[3]), "r"(b[0]), "r"(b[1]));
}
__device__ __forceinline__ void cp16(void* dst, const void* src) {
    unsigned d = (unsigned)__cvta_generic_to_shared(dst);
    asm volatile("cp.async.cg.shared.global [%0], [%1], 16;" :: "r"(d), "l"(src));
}
__device__ __forceinline__ void cpcommit() { asm volatile("cp.async.commit_group;"); }
template<int N> __device__ __forceinline__ void cpwait() {
    asm volatile("cp.async.wait_group %0;" :: "n"(N));
}

// =================================================================
// Projection GEMM: C[M,512] = A[M,512] @ W[512,512] (+bias)(+resid)
// 128x128 tile, BK=32, 8 warps (2m x 4n), warp tile 64x32, cp.async 2-deep.
// HID_A: A element (m=b*4096+n, c) = hid[b][c][n]. ROUND: write tf32-rounded.
// =================================================================
template<bool HID_A, bool ROUND>
__global__ __launch_bounds__(256, 2)
void gemm128ca(const float* __restrict__ A, const float* __restrict__ W,
               const float* __restrict__ bias, const float* __restrict__ resid,
               float* __restrict__ C)
{
    extern __shared__ float sm[];
    float* Abase = sm;
    float* Bbase = sm + (HID_A ? 2 * 32 * 136 : 2 * 128 * 36);

    const int tid = threadIdx.x;
    const int m0 = blockIdx.y * 128, j0 = blockIdx.x * 128;
    const int w = tid >> 5, lane = tid & 31, g = lane >> 2, tig = lane & 3;
    const int mw = (w >> 2) * 64, nw = (w & 3) * 32;

    auto loadA = [&](int buf, int c0) {
        if (HID_A) {
            float* dst = Abase + buf * 32 * 136;
            const int bb = m0 >> 12, n0 = m0 & 4095;
            #pragma unroll
            for (int i = 0; i < 4; i++) {
                int id = tid + i * 256;
                int k = id >> 5, m4 = (id & 31) * 4;
                cp16(dst + k * 136 + m4,
                     A + ((size_t)(bb * 512 + c0 + k)) * 4096 + n0 + m4);
            }
        } else {
            float* dst = Abase + buf * 128 * 36;
            #pragma unroll
            for (int i = 0; i < 4; i++) {
                int id = tid + i * 256;
                int m = id >> 3, c4 = (id & 7) * 4;
                cp16(dst + m * 36 + c4, A + (size_t)(m0 + m) * 512 + c0 + c4);
            }
        }
    };
    auto loadB = [&](int buf, int c0) {
        float* dst = Bbase + buf * 32 * 136;
        #pragma unroll
        for (int i = 0; i < 4; i++) {
            int id = tid + i * 256;
            int k = id >> 5, n4 = (id & 31) * 4;
            cp16(dst + k * 136 + n4, W + (size_t)(c0 + k) * 512 + j0 + n4);
        }
    };

    float acc[4][4][4];
    #pragma unroll
    for (int i = 0; i < 4; i++)
        #pragma unroll
        for (int j = 0; j < 4; j++)
            #pragma unroll
            for (int r = 0; r < 4; r++) acc[i][j][r] = 0.f;

    loadA(0, 0); loadB(0, 0); cpcommit();
    for (int t = 0; t < 16; t++) {
        const int buf = t & 1;
        if (t < 15) { loadA(buf ^ 1, (t + 1) * 32); loadB(buf ^ 1, (t + 1) * 32); cpcommit(); cpwait<1>(); }
        else cpwait<0>();
        __syncthreads();
        const float* As = HID_A ? (Abase + buf * 32 * 136) : (Abase + buf * 128 * 36);
        const float* Bs = Bbase + buf * 32 * 136;
        #pragma unroll
        for (int k8 = 0; k8 < 4; k8++) {
            const int kb = k8 * 8 + tig;
            unsigned af[4][4], bf[4][2];
            #pragma unroll
            for (int im = 0; im < 4; im++) {
                const int r = mw + im * 16 + g;
                if (HID_A) {
                    af[im][0] = f2tf(As[kb * 136 + r]);
                    af[im][1] = f2tf(As[kb * 136 + r + 8]);
                    af[im][2] = f2tf(As[(kb + 4) * 136 + r]);
                    af[im][3] = f2tf(As[(kb + 4) * 136 + r + 8]);
                } else {
                    af[im][0] = f2tf(As[r * 36 + kb]);
                    af[im][1] = f2tf(As[(r + 8) * 36 + kb]);
                    af[im][2] = f2tf(As[r * 36 + kb + 4]);
                    af[im][3] = f2tf(As[(r + 8) * 36 + kb + 4]);
                }
            }
            #pragma unroll
            for (int jn = 0; jn < 4; jn++) {
                const int n = nw + jn * 8 + g;
                bf[jn][0] = f2tf(Bs[kb * 136 + n]);
                bf[jn][1] = f2tf(Bs[(kb + 4) * 136 + n]);
            }
            #pragma unroll
            for (int im = 0; im < 4; im++)
                #pragma unroll
                for (int jn = 0; jn < 4; jn++)
                    mma_tf32(acc[im][jn], af[im], bf[jn]);
        }
        __syncthreads();
    }
    #pragma unroll
    for (int im = 0; im < 4; im++) {
        #pragma unroll
        for (int jn = 0; jn < 4; jn++) {
            const int r0 = m0 + mw + im * 16 + g;
            const int col = j0 + nw + jn * 8 + 2 * tig;
            const float* cc = acc[im][jn];
            #pragma unroll
            for (int half = 0; half < 2; half++) {
                const int r = r0 + half * 8;
                float v0 = cc[half * 2]     + bias[col];
                float v1 = cc[half * 2 + 1] + bias[col + 1];
                if (resid) {
                    v0 += resid[(size_t)r * 512 + col];
                    v1 += resid[(size_t)r * 512 + col + 1];
                }
                if (ROUND) { v0 = __uint_as_float(f2tf(v0)); v1 = __uint_as_float(f2tf(v1)); }
                *(float2*)(C + (size_t)r * 512 + col) = make_float2(v0, v1);
            }
        }
    }
}

// =================================================================
// S tile mma: qf (tf32 bits) x K buffer (tf32 bits, stride 68 words)
// =================================================================
__device__ __forceinline__ void mma_S(float s[8][4], const unsigned* Kbuf,
                                      const unsigned qf[8][4], int g, int tig) {
    #pragma unroll
    for (int jn = 0; jn < 8; jn++) { s[jn][0] = s[jn][1] = s[jn][2] = s[jn][3] = 0.f; }
    #pragma unroll
    for (int ks = 0; ks < 8; ks++) {
        const int kb = ks * 8 + tig;
        #pragma unroll
        for (int jn = 0; jn < 8; jn++) {
            unsigned bf[2];
            bf[0] = Kbuf[(jn * 8 + g) * 68 + kb];
            bf[1] = Kbuf[(jn * 8 + g) * 68 + kb + 4];
            mma_tf32(s[jn], qf[ks], bf);
        }
    }
}

__device__ __forceinline__ void load_qf(unsigned qf[8][4], const float* Qp, int r0, int tig) {
    #pragma unroll
    for (int ks = 0; ks < 8; ks++) {
        qf[ks][0] = f2tf(0.125f * Qp[(size_t)r0 * 512 + ks * 8 + tig]);
        qf[ks][1] = f2tf(0.125f * Qp[(size_t)(r0 + 8) * 512 + ks * 8 + tig]);
        qf[ks][2] = f2tf(0.125f * Qp[(size_t)r0 * 512 + ks * 8 + tig + 4]);
        qf[ks][3] = f2tf(0.125f * Qp[(size_t)(r0 + 8) * 512 + ks * 8 + tig + 4]);
    }
}

// =================================================================
// Pass 1: per (qtile, bh, key-half): online row max / sum over 2048 keys.
// block = 128 thr (4 warps x 16 rows), grid = (4, 64, 2)
// =================================================================
__global__ __launch_bounds__(128, 3)
void flash_pass1(const float* __restrict__ gq, const float* __restrict__ gk,
                 float* __restrict__ ml)
{
    extern __shared__ unsigned smu[];
    unsigned* Ks = smu;                      // [2][64][68]

    const int tid = threadIdx.x;
    const int w = tid >> 5, lane = tid & 31, g = lane >> 2, tig = lane & 3;
    const int z = blockIdx.y, b = z >> 3, h = z & 7;
    const int m0 = blockIdx.x * 64;
    const int half = blockIdx.z;
    const float* Qp = gq + ((size_t)(b * 256 + m0)) * 512 + h * 64;
    const float* Kp = gk + (size_t)b * HW * 512 + h * 64 + (size_t)half * 2048 * 512;
    const int r0 = w * 16 + g;

    unsigned qf[8][4];
    load_qf(qf, Qp, r0, tig);

    auto loadK = [&](int buf, int kt) {
        unsigned* dst = Ks + buf * 64 * 68;
        const float* src = Kp + (size_t)kt * 64 * 512;
        #pragma unroll
        for (int i = 0; i < 8; i++) {
            int id = tid + i * 128;
            int row = id >> 4, c4 = (id & 15) * 4;
            cp16(dst + row * 68 + c4, src + (size_t)row * 512 + c4);
        }
    };

    float m[2] = {-1e30f, -1e30f}, l[2] = {0.f, 0.f};

    loadK(0, 0); cpcommit();
    for (int kt = 0; kt < 32; kt++) {
        const int buf = kt & 1;
        if (kt < 31) { loadK(buf ^ 1, kt + 1); cpcommit(); cpwait<1>(); }
        else cpwait<0>();
        __syncthreads();
        float s[8][4];
        mma_S(s, Ks + buf * 64 * 68, qf, g, tig);
        #pragma unroll
        for (int rr = 0; rr < 2; rr++) {
            float mx = -1e30f;
            #pragma unroll
            for (int jn = 0; jn < 8; jn++)
                mx = fmaxf(mx, fmaxf(s[jn][2 * rr], s[jn][2 * rr + 1]));
            mx = fmaxf(mx, __shfl_xor_sync(0xffffffffu, mx, 1));
            mx = fmaxf(mx, __shfl_xor_sync(0xffffffffu, mx, 2));
            const float mn = fmaxf(m[rr], mx);
            float sum = 0.f;
            #pragma unroll
            for (int jn = 0; jn < 8; jn++)
                sum += __expf(s[jn][2 * rr] - mn) + __expf(s[jn][2 * rr + 1] - mn);
            sum += __shfl_xor_sync(0xffffffffu, sum, 1);
            sum += __shfl_xor_sync(0xffffffffu, sum, 2);
            l[rr] = l[rr] * __expf(m[rr] - mn) + sum;
            m[rr] = mn;
        }
        __syncthreads();
    }
    if (tig == 0) {
        float* dst = ml + (((size_t)(z * 4 + blockIdx.x) * 2 + half) * 64) * 2;
        dst[r0 * 2]           = m[0];
        dst[r0 * 2 + 1]       = l[0];
        dst[(r0 + 8) * 2]     = m[1];
        dst[(r0 + 8) * 2 + 1] = l[1];
    }
}

// =================================================================
// Pass 2: merge (m,l) halves -> global; P = exp(S-m)/l -> attn + smem (tf32
// bits); partial O += P @ V for this key-half. grid = (4, 64, 2)
// =================================================================
__global__ __launch_bounds__(128, 2)
void flash_pass2(const float* __restrict__ gq, const float* __restrict__ gk,
                 const float* __restrict__ gv, const float* __restrict__ ml,
                 float* __restrict__ attn, float* __restrict__ aop)
{
    extern __shared__ unsigned smu[];
    unsigned* Ks = smu;                              // [2][64][68]
    unsigned* Vs = smu + 2 * 64 * 68;                // [2][64][72]
    unsigned* Ps = smu + 2 * 64 * 68 + 2 * 64 * 72;  // [4][16][68]

    const int tid = threadIdx.x;
    const int w = tid >> 5, lane = tid & 31, g = lane >> 2, tig = lane & 3;
    const int z = blockIdx.y, b = z >> 3, h = z & 7;
    const int m0 = blockIdx.x * 64;
    const int half = blockIdx.z;
    const float* Qp = gq + ((size_t)(b * 256 + m0)) * 512 + h * 64;
    const float* Kp = gk + (size_t)b * HW * 512 + h * 64 + (size_t)half * 2048 * 512;
    const float* Vp = gv + (size_t)b * HW * 512 + h * 64 + (size_t)half * 2048 * 512;
    float* Ap = attn + (size_t)z * NK * HW + (size_t)m0 * HW + half * 2048;
    float* Op = aop + (size_t)half * 2048 * 512 + ((size_t)(b * 256 + m0)) * 512 + h * 64;
    const int r0 = w * 16 + g;

    unsigned qf[8][4];
    load_qf(qf, Qp, r0, tig);

    // merge (m,l) from both halves -> global m, invl per row
    float mg[2], invl[2];
    {
        const float* ml0 = ml + ((size_t)(z * 4 + blockIdx.x) * 2) * 128;
        const float* ml1 = ml0 + 128;
        #pragma unroll
        for (int rr = 0; rr < 2; rr++) {
            const int row = r0 + rr * 8;
            float m0v = ml0[row * 2], l0v = ml0[row * 2 + 1];
            float m1v = ml1[row * 2], l1v = ml1[row * 2 + 1];
            float mm = fmaxf(m0v, m1v);
            float ll = l0v * __expf(m0v - mm) + l1v * __expf(m1v - mm);
            mg[rr] = mm;
            invl[rr] = 1.f / ll;
        }
    }

    auto loadK = [&](int buf, int kt) {
        unsigned* dst = Ks + buf * 64 * 68;
        const float* src = Kp + (size_t)kt * 64 * 512;
        #pragma unroll
        for (int i = 0; i < 8; i++) {
            int id = tid + i * 128;
            int row = id >> 4, c4 = (id & 15) * 4;
            cp16(dst + row * 68 + c4, src + (size_t)row * 512 + c4);
        }
    };
    auto loadV = [&](int buf, int kt) {
        unsigned* dst = Vs + buf * 64 * 72;
        const float* src = Vp + (size_t)kt * 64 * 512;
        #pragma unroll
        for (int i = 0; i < 8; i++) {
            int id = tid + i * 128;
            int row = id >> 4, c4 = (id & 15) * 4;
            cp16(dst + row * 72 + c4, src + (size_t)row * 512 + c4);
        }
    };

    float o[8][4];
    #pragma unroll
    for (int jn = 0; jn < 8; jn++)
        #pragma unroll
        for (int r = 0; r < 4; r++) o[jn][r] = 0.f;

    loadK(0, 0); loadV(0, 0); cpcommit();
    unsigned* Pw = Ps + w * 16 * 68;
    for (int kt = 0; kt < 32; kt++) {
        const int buf = kt & 1;
        if (kt < 31) { loadK(buf ^ 1, kt + 1); loadV(buf ^ 1, kt + 1); cpcommit(); cpwait<1>(); }
        else cpwait<0>();
        __syncthreads();
        float s[8][4];
        mma_S(s, Ks + buf * 64 * 68, qf, g, tig);
        #pragma unroll
        for (int jn = 0; jn < 8; jn++) {
            const float p0 = __expf(s[jn][0] - mg[0]) * invl[0];
            const float p1 = __expf(s[jn][1] - mg[0]) * invl[0];
            const float p2 = __expf(s[jn][2] - mg[1]) * invl[1];
            const float p3 = __expf(s[jn][3] - mg[1]) * invl[1];
            const int col = jn * 8 + 2 * tig;
            *(float2*)(Ap + (size_t)r0 * HW + kt * 64 + col)       = make_float2(p0, p1);
            *(float2*)(Ap + (size_t)(r0 + 8) * HW + kt * 64 + col) = make_float2(p2, p3);
            Pw[g * 68 + col]           = f2tf(p0);
            Pw[g * 68 + col + 1]       = f2tf(p1);
            Pw[(g + 8) * 68 + col]     = f2tf(p2);
            Pw[(g + 8) * 68 + col + 1] = f2tf(p3);
        }
        __syncwarp();
        const unsigned* Vb = Vs + buf * 64 * 72;
        #pragma unroll
        for (int ks = 0; ks < 8; ks++) {
            const int kb = ks * 8 + tig;
            unsigned af[4];
            af[0] = Pw[g * 68 + kb];
            af[1] = Pw[(g + 8) * 68 + kb];
            af[2] = Pw[g * 68 + kb + 4];
            af[3] = Pw[(g + 8) * 68 + kb + 4];
            #pragma unroll
            for (int jn = 0; jn < 8; jn++) {
                const int n = jn * 8 + g;
                unsigned bf[2];
                bf[0] = Vb[kb * 72 + n];
                bf[1] = Vb[(kb + 4) * 72 + n];
                mma_tf32(o[jn], af, bf);
            }
        }
        __syncthreads();
    }
    #pragma unroll
    for (int jn = 0; jn < 8; jn++) {
        const int col = jn * 8 + 2 * tig;
        *(float2*)(Op + (size_t)r0 * 512 + col)       = make_float2(o[jn][0], o[jn][1]);
        *(float2*)(Op + (size_t)(r0 + 8) * 512 + col) = make_float2(o[jn][2], o[jn][3]);
    }
}

// =================================================================
__global__ void add_ao(const float4* __restrict__ a, const float4* __restrict__ b,
                       float4* __restrict__ c) {
    const int i = blockIdx.x * 512 + threadIdx.x;
    float4 x = a[i], y = b[i];
    c[i] = make_float4(x.x + y.x, x.y + y.y, x.z + y.z, x.w + y.w);
}

// =================================================================
__global__ void ln_kernel(const float* __restrict__ x, const float* __restrict__ g,
                          const float* __restrict__ bb, float* __restrict__ out) {
    __shared__ float red[8];
    const int row = blockIdx.x, t = threadIdx.x;
    const float* xr = x + (size_t)row * 512;
    const float v0 = xr[t], v1 = xr[t + 256];
    float s = v0 + v1;
    #pragma unroll
    for (int o = 16; o; o >>= 1) s += __shfl_xor_sync(0xffffffffu, s, o);
    if ((t & 31) == 0) red[t >> 5] = s;
    __syncthreads();
    float tot = 0.f;
    #pragma unroll
    for (int i = 0; i < 8; i++) tot += red[i];
    const float mu = tot * (1.0f / 512.0f);
    const float d0 = v0 - mu, d1 = v1 - mu;
    float q = d0 * d0 + d1 * d1;
    __syncthreads();
    #pragma unroll
    for (int o = 16; o; o >>= 1) q += __shfl_xor_sync(0xffffffffu, q, o);
    if ((t & 31) == 0) red[t >> 5] = q;
    __syncthreads();
    tot = 0.f;
    #pragma unroll
    for (int i = 0; i < 8; i++) tot += red[i];
    const float inv = rsqrtf(tot * (1.0f / 512.0f) + 1e-5f);
    out[(size_t)row * 512 + t]       = d0 * inv * g[t] + bb[t];
    out[(size_t)row * 512 + t + 256] = d1 * inv * g[t + 256] + bb[t + 256];
}

// =================================================================
static const int SMEM_PROJ_N = (2 * 128 * 36 + 2 * 32 * 136) * 4;
static const int SMEM_PROJ_H = (2 * 32 * 136 + 2 * 32 * 136) * 4;
static const int SMEM_P1 = 2 * 64 * 68 * 4;
static const int SMEM_P2 = (2 * 64 * 68 + 2 * 64 * 72 + 4 * 16 * 68) * 4;

extern "C" void kernel_launch(void* const* d_in, const int* in_sizes, int n_in,
                              void* d_out, int out_size) {
    const float* hidden = (const float*)d_in[0];
    const float* aux    = (const float*)d_in[1];
    const float* Wq = (const float*)d_in[2];
    const float* bq = (const float*)d_in[3];
    const float* Wk = (const float*)d_in[4];
    const float* bk = (const float*)d_in[5];
    const float* Wv = (const float*)d_in[6];
    const float* bv = (const float*)d_in[7];
    const float* Wo = (const float*)d_in[8];
    const float* bo = (const float*)d_in[9];
    const float* lng = (const float*)d_in[10];
    const float* lnb = (const float*)d_in[11];
    float* out = (float*)d_out;

    float *gq, *gk, *gv, *gao, *gaop, *gx, *gml;
    cudaGetSymbolAddress((void**)&gq,   g_q);
    cudaGetSymbolAddress((void**)&gk,   g_k);
    cudaGetSymbolAddress((void**)&gv,   g_v);
    cudaGetSymbolAddress((void**)&gao,  g_ao);
    cudaGetSymbolAddress((void**)&gaop, g_aop);
    cudaGetSymbolAddress((void**)&gx,   g_x);
    cudaGetSymbolAddress((void**)&gml,  g_ml);

    const size_t AUXOUT = (size_t)2048 * 512;
    const size_t ATTN_N = (size_t)64 * 256 * 4096;
    float* attn;
    if ((size_t)out_size >= AUXOUT + ATTN_N) attn = out + AUXOUT;
    else cudaGetSymbolAddress((void**)&attn, g_attn_fb);

    static bool attrs_set = false;
    if (!attrs_set) {
        cudaFuncSetAttribute((const void*)gemm128ca<false, false>, cudaFuncAttributeMaxDynamicSharedMemorySize, SMEM_PROJ_N);
        cudaFuncSetAttribute((const void*)gemm128ca<true, true>,   cudaFuncAttributeMaxDynamicSharedMemorySize, SMEM_PROJ_H);
        cudaFuncSetAttribute((const void*)flash_pass1,             cudaFuncAttributeMaxDynamicSharedMemorySize, SMEM_P1);
        cudaFuncSetAttribute((const void*)flash_pass2,             cudaFuncAttributeMaxDynamicSharedMemorySize, SMEM_P2);
        attrs_set = true;
    }

    // Q projection
    gemm128ca<false, false><<<dim3(4, 16), 256, SMEM_PROJ_N>>>(aux, Wq, bq, nullptr, gq);
    // K / V projections (tf32-rounded outputs)
    gemm128ca<true, true><<<dim3(4, 256), 256, SMEM_PROJ_H>>>(hidden, Wk, bk, nullptr, gk);
    gemm128ca<true, true><<<dim3(4, 256), 256, SMEM_PROJ_H>>>(hidden, Wv, bv, nullptr, gv);
    // attention, split over 2 key-halves
    flash_pass1<<<dim3(4, 64, 2), 128, SMEM_P1>>>(gq, gk, gml);
    flash_pass2<<<dim3(4, 64, 2), 128, SMEM_P2>>>(gq, gk, gv, gml, attn, gaop);
    add_ao<<<512, 512>>>((const float4*)gaop, (const float4*)(gaop + AUXOUT), (float4*)gao);
    // out-proj + residual
    gemm128ca<false, false><<<dim3(4, 16), 256, SMEM_PROJ_N>>>(gao, Wo, bo, aux, gx);
    // LayerNorm
    ln_kernel<<<2048, 256>>>(gx, lng, lnb, out);
}

// round 5
// speedup vs baseline: 6.1573x; 1.0716x over previous
#include <cuda_runtime.h>
#include <cstddef>

#define HW    4096
#define NK    256
#define DIM   512
#define NSPL  4   // key splits for attention

// ---------------- scratch (no allocation allowed) ----------------
__device__ float g_q [2048u  * 512u];
__device__ float g_k [32768u * 512u];   // tf32-rounded bits
__device__ float g_v [32768u * 512u];   // tf32-rounded bits
__device__ float g_ao [2048u * 512u];
__device__ float g_aop[4u * 2048u * 512u];        // partial O per key-quarter
__device__ float g_x [2048u  * 512u];
__device__ float g_ml[64u * 4u * 4u * 64u * 2u];  // (z,qtile,quarter,row,{m,l})
__device__ float g_attn_fb[(size_t)64 * 256 * 4096];

// ---------------- helpers ----------------
__device__ __forceinline__ unsigned f2tf(float x) {
    unsigned r;
    asm("cvt.rna.tf32.f32 %0, %1;" : "=r"(r) : "f"(x));
    return r;
}
__device__ __forceinline__ void mma_tf32(float* c, const unsigned* a, const unsigned* b) {
    asm volatile(
        "mma.sync.aligned.m16n8k8.row.col.f32.tf32.tf32.f32 "
        "{%0,%1,%2,%3}, {%4,%5,%6,%7}, {%8,%9}, {%0,%1,%2,%3};\n"
        : "+f"(c[0]), "+f"(c[1]), "+f"(c[2]), "+f"(c[3])
        : "r"(a[0]), "r"(a[1]), "r"(a[2]), "r"(a[3]), "r"(b[0]), "r"(b[1]));
}
__device__ __forceinline__ void cp16(void* dst, const void* src) {
    unsigned d = (unsigned)__cvta_generic_to_shared(dst);
    asm volatile("cp.async.cg.shared.global [%0], [%1], 16;" :: "r"(d), "l"(src));
}
__device__ __forceinline__ void cpcommit() { asm volatile("cp.async.commit_group;"); }
template<int N> __device__ __forceinline__ void cpwait() {
    asm volatile("cp.async.wait_group %0;" :: "n"(N));
}

// =================================================================
// Projection GEMM: C[M,512] = A[M,512] @ W[512,512] (+bias)(+resid)
// 128x128 CTA tile, BK=32, 4 warps (2m x 2n), warp tile 64x64.
// cp.async 2-deep. HID_A: A(m=b*4096+n, c) = hid[b][c][n].
// ROUND: write tf32-rounded output.
// =================================================================
template<bool HID_A, bool ROUND>
__global__ __launch_bounds__(128, 2)
void gemm128ca(const float* __restrict__ A, const float* __restrict__ W,
               const float* __restrict__ bias, const float* __restrict__ resid,
               float* __restrict__ C)
{
    extern __shared__ float sm[];
    float* Abase = sm;
    float* Bbase = sm + (HID_A ? 2 * 32 * 136 : 2 * 128 * 36);

    const int tid = threadIdx.x;
    const int m0 = blockIdx.y * 128, j0 = blockIdx.x * 128;
    const int w = tid >> 5, lane = tid & 31, g = lane >> 2, tig = lane & 3;
    const int mw = (w >> 1) * 64, nw = (w & 1) * 64;

    auto loadA = [&](int buf, int c0) {
        if (HID_A) {
            float* dst = Abase + buf * 32 * 136;
            const int bb = m0 >> 12, n0 = m0 & 4095;
            #pragma unroll
            for (int i = 0; i < 8; i++) {
                int id = tid + i * 128;
                int k = id >> 5, m4 = (id & 31) * 4;
                cp16(dst + k * 136 + m4,
                     A + ((size_t)(bb * 512 + c0 + k)) * 4096 + n0 + m4);
            }
        } else {
            float* dst = Abase + buf * 128 * 36;
            #pragma unroll
            for (int i = 0; i < 8; i++) {
                int id = tid + i * 128;
                int m = id >> 3, c4 = (id & 7) * 4;
                cp16(dst + m * 36 + c4, A + (size_t)(m0 + m) * 512 + c0 + c4);
            }
        }
    };
    auto loadB = [&](int buf, int c0) {
        float* dst = Bbase + buf * 32 * 136;
        #pragma unroll
        for (int i = 0; i < 8; i++) {
            int id = tid + i * 128;
            int k = id >> 5, n4 = (id & 31) * 4;
            cp16(dst + k * 136 + n4, W + (size_t)(c0 + k) * 512 + j0 + n4);
        }
    };

    float acc[4][8][4];
    #pragma unroll
    for (int i = 0; i < 4; i++)
        #pragma unroll
        for (int j = 0; j < 8; j++)
            #pragma unroll
            for (int r = 0; r < 4; r++) acc[i][j][r] = 0.f;

    loadA(0, 0); loadB(0, 0); cpcommit();
    for (int t = 0; t < 16; t++) {
        const int buf = t & 1;
        if (t < 15) { loadA(buf ^ 1, (t + 1) * 32); loadB(buf ^ 1, (t + 1) * 32); cpcommit(); cpwait<1>(); }
        else cpwait<0>();
        __syncthreads();
        const float* As = HID_A ? (Abase + buf * 32 * 136) : (Abase + buf * 128 * 36);
        const float* Bs = Bbase + buf * 32 * 136;
        #pragma unroll
        for (int k8 = 0; k8 < 4; k8++) {
            const int kb = k8 * 8 + tig;
            unsigned af[4][4], bf[8][2];
            #pragma unroll
            for (int im = 0; im < 4; im++) {
                const int r = mw + im * 16 + g;
                if (HID_A) {
                    af[im][0] = f2tf(As[kb * 136 + r]);
                    af[im][1] = f2tf(As[kb * 136 + r + 8]);
                    af[im][2] = f2tf(As[(kb + 4) * 136 + r]);
                    af[im][3] = f2tf(As[(kb + 4) * 136 + r + 8]);
                } else {
                    af[im][0] = f2tf(As[r * 36 + kb]);
                    af[im][1] = f2tf(As[(r + 8) * 36 + kb]);
                    af[im][2] = f2tf(As[r * 36 + kb + 4]);
                    af[im][3] = f2tf(As[(r + 8) * 36 + kb + 4]);
                }
            }
            #pragma unroll
            for (int jn = 0; jn < 8; jn++) {
                const int n = nw + jn * 8 + g;
                bf[jn][0] = f2tf(Bs[kb * 136 + n]);
                bf[jn][1] = f2tf(Bs[(kb + 4) * 136 + n]);
            }
            #pragma unroll
            for (int im = 0; im < 4; im++)
                #pragma unroll
                for (int jn = 0; jn < 8; jn++)
                    mma_tf32(acc[im][jn], af[im], bf[jn]);
        }
        __syncthreads();
    }
    #pragma unroll
    for (int im = 0; im < 4; im++) {
        #pragma unroll
        for (int jn = 0; jn < 8; jn++) {
            const int r0 = m0 + mw + im * 16 + g;
            const int col = j0 + nw + jn * 8 + 2 * tig;
            const float* cc = acc[im][jn];
            #pragma unroll
            for (int half = 0; half < 2; half++) {
                const int r = r0 + half * 8;
                float v0 = cc[half * 2]     + bias[col];
                float v1 = cc[half * 2 + 1] + bias[col + 1];
                if (resid) {
                    v0 += resid[(size_t)r * 512 + col];
                    v1 += resid[(size_t)r * 512 + col + 1];
                }
                if (ROUND) { v0 = __uint_as_float(f2tf(v0)); v1 = __uint_as_float(f2tf(v1)); }
                *(float2*)(C + (size_t)r * 512 + col) = make_float2(v0, v1);
            }
        }
    }
}

// =================================================================
// S tile mma: qf (tf32 bits) x K buffer (tf32 bits, stride 68 words)
// =================================================================
__device__ __forceinline__ void mma_S(float s[8][4], const unsigned* Kbuf,
                                      const unsigned qf[8][4], int g, int tig) {
    #pragma unroll
    for (int jn = 0; jn < 8; jn++) { s[jn][0] = s[jn][1] = s[jn][2] = s[jn][3] = 0.f; }
    #pragma unroll
    for (int ks = 0; ks < 8; ks++) {
        const int kb = ks * 8 + tig;
        #pragma unroll
        for (int jn = 0; jn < 8; jn++) {
            unsigned bf[2];
            bf[0] = Kbuf[(jn * 8 + g) * 68 + kb];
            bf[1] = Kbuf[(jn * 8 + g) * 68 + kb + 4];
            mma_tf32(s[jn], qf[ks], bf);
        }
    }
}

__device__ __forceinline__ void load_qf(unsigned qf[8][4], const float* Qp, int r0, int tig) {
    #pragma unroll
    for (int ks = 0; ks < 8; ks++) {
        qf[ks][0] = f2tf(0.125f * Qp[(size_t)r0 * 512 + ks * 8 + tig]);
        qf[ks][1] = f2tf(0.125f * Qp[(size_t)(r0 + 8) * 512 + ks * 8 + tig]);
        qf[ks][2] = f2tf(0.125f * Qp[(size_t)r0 * 512 + ks * 8 + tig + 4]);
        qf[ks][3] = f2tf(0.125f * Qp[(size_t)(r0 + 8) * 512 + ks * 8 + tig + 4]);
    }
}

// =================================================================
// Pass 1: per (qtile, bh, key-quarter): online row max / sum over 1024 keys.
// block = 128 thr (4 warps x 16 rows), grid = (4, 64, 4)
// =================================================================
__global__ __launch_bounds__(128, 4)
void flash_pass1(const float* __restrict__ gq, const float* __restrict__ gk,
                 float* __restrict__ ml)
{
    extern __shared__ unsigned smu[];
    unsigned* Ks = smu;                      // [2][64][68]

    const int tid = threadIdx.x;
    const int w = tid >> 5, lane = tid & 31, g = lane >> 2, tig = lane & 3;
    const int z = blockIdx.y, b = z >> 3, h = z & 7;
    const int m0 = blockIdx.x * 64;
    const int qu = blockIdx.z;
    const float* Qp = gq + ((size_t)(b * 256 + m0)) * 512 + h * 64;
    const float* Kp = gk + (size_t)b * HW * 512 + h * 64 + (size_t)qu * 1024 * 512;
    const int r0 = w * 16 + g;

    unsigned qf[8][4];
    load_qf(qf, Qp, r0, tig);

    auto loadK = [&](int buf, int kt) {
        unsigned* dst = Ks + buf * 64 * 68;
        const float* src = Kp + (size_t)kt * 64 * 512;
        #pragma unroll
        for (int i = 0; i < 8; i++) {
            int id = tid + i * 128;
            int row = id >> 4, c4 = (id & 15) * 4;
            cp16(dst + row * 68 + c4, src + (size_t)row * 512 + c4);
        }
    };

    float m[2] = {-1e30f, -1e30f}, l[2] = {0.f, 0.f};

    loadK(0, 0); cpcommit();
    for (int kt = 0; kt < 16; kt++) {
        const int buf = kt & 1;
        if (kt < 15) { loadK(buf ^ 1, kt + 1); cpcommit(); cpwait<1>(); }
        else cpwait<0>();
        __syncthreads();
        float s[8][4];
        mma_S(s, Ks + buf * 64 * 68, qf, g, tig);
        #pragma unroll
        for (int rr = 0; rr < 2; rr++) {
            float mx = -1e30f;
            #pragma unroll
            for (int jn = 0; jn < 8; jn++)
                mx = fmaxf(mx, fmaxf(s[jn][2 * rr], s[jn][2 * rr + 1]));
            mx = fmaxf(mx, __shfl_xor_sync(0xffffffffu, mx, 1));
            mx = fmaxf(mx, __shfl_xor_sync(0xffffffffu, mx, 2));
            const float mn = fmaxf(m[rr], mx);
            float sum = 0.f;
            #pragma unroll
            for (int jn = 0; jn < 8; jn++)
                sum += __expf(s[jn][2 * rr] - mn) + __expf(s[jn][2 * rr + 1] - mn);
            sum += __shfl_xor_sync(0xffffffffu, sum, 1);
            sum += __shfl_xor_sync(0xffffffffu, sum, 2);
            l[rr] = l[rr] * __expf(m[rr] - mn) + sum;
            m[rr] = mn;
        }
        __syncthreads();
    }
    if (tig == 0) {
        float* dst = ml + (((size_t)(z * 4 + blockIdx.x) * NSPL + qu) * 64) * 2;
        dst[r0 * 2]           = m[0];
        dst[r0 * 2 + 1]       = l[0];
        dst[(r0 + 8) * 2]     = m[1];
        dst[(r0 + 8) * 2 + 1] = l[1];
    }
}

// =================================================================
// Pass 2: merge (m,l) quarters -> global; P = exp(S-m)/l -> attn + smem
// (tf32 bits); partial O += P @ V for this key-quarter. grid = (4, 64, 4)
// =================================================================
__global__ __launch_bounds__(128, 2)
void flash_pass2(const float* __restrict__ gq, const float* __restrict__ gk,
                 const float* __restrict__ gv, const float* __restrict__ ml,
                 float* __restrict__ attn, float* __restrict__ aop)
{
    extern __shared__ unsigned smu[];
    unsigned* Ks = smu;                              // [2][64][68]
    unsigned* Vs = smu + 2 * 64 * 68;                // [2][64][72]
    unsigned* Ps = smu + 2 * 64 * 68 + 2 * 64 * 72;  // [4][16][68]

    const int tid = threadIdx.x;
    const int w = tid >> 5, lane = tid & 31, g = lane >> 2, tig = lane & 3;
    const int z = blockIdx.y, b = z >> 3, h = z & 7;
    const int m0 = blockIdx.x * 64;
    const int qu = blockIdx.z;
    const float* Qp = gq + ((size_t)(b * 256 + m0)) * 512 + h * 64;
    const float* Kp = gk + (size_t)b * HW * 512 + h * 64 + (size_t)qu * 1024 * 512;
    const float* Vp = gv + (size_t)b * HW * 512 + h * 64 + (size_t)qu * 1024 * 512;
    float* Ap = attn + (size_t)z * NK * HW + (size_t)m0 * HW + qu * 1024;
    float* Op = aop + (size_t)qu * 2048 * 512 + ((size_t)(b * 256 + m0)) * 512 + h * 64;
    const int r0 = w * 16 + g;

    unsigned qf[8][4];
    load_qf(qf, Qp, r0, tig);

    // merge (m,l) from all quarters -> global m, invl per row
    float mg[2], invl[2];
    {
        const float* mlb = ml + ((size_t)(z * 4 + blockIdx.x) * NSPL) * 128;
        #pragma unroll
        for (int rr = 0; rr < 2; rr++) {
            const int row = r0 + rr * 8;
            float mm = -1e30f;
            #pragma unroll
            for (int q = 0; q < NSPL; q++) mm = fmaxf(mm, mlb[q * 128 + row * 2]);
            float ll = 0.f;
            #pragma unroll
            for (int q = 0; q < NSPL; q++)
                ll += mlb[q * 128 + row * 2 + 1] * __expf(mlb[q * 128 + row * 2] - mm);
            mg[rr] = mm;
            invl[rr] = 1.f / ll;
        }
    }

    auto loadK = [&](int buf, int kt) {
        unsigned* dst = Ks + buf * 64 * 68;
        const float* src = Kp + (size_t)kt * 64 * 512;
        #pragma unroll
        for (int i = 0; i < 8; i++) {
            int id = tid + i * 128;
            int row = id >> 4, c4 = (id & 15) * 4;
            cp16(dst + row * 68 + c4, src + (size_t)row * 512 + c4);
        }
    };
    auto loadV = [&](int buf, int kt) {
        unsigned* dst = Vs + buf * 64 * 72;
        const float* src = Vp + (size_t)kt * 64 * 512;
        #pragma unroll
        for (int i = 0; i < 8; i++) {
            int id = tid + i * 128;
            int row = id >> 4, c4 = (id & 15) * 4;
            cp16(dst + row * 72 + c4, src + (size_t)row * 512 + c4);
        }
    };

    float o[8][4];
    #pragma unroll
    for (int jn = 0; jn < 8; jn++)
        #pragma unroll
        for (int r = 0; r < 4; r++) o[jn][r] = 0.f;

    loadK(0, 0); loadV(0, 0); cpcommit();
    unsigned* Pw = Ps + w * 16 * 68;
    for (int kt = 0; kt < 16; kt++) {
        const int buf = kt & 1;
        if (kt < 15) { loadK(buf ^ 1, kt + 1); loadV(buf ^ 1, kt + 1); cpcommit(); cpwait<1>(); }
        else cpwait<0>();
        __syncthreads();
        float s[8][4];
        mma_S(s, Ks + buf * 64 * 68, qf, g, tig);
        #pragma unroll
        for (int jn = 0; jn < 8; jn++) {
            const float p0 = __expf(s[jn][0] - mg[0]) * invl[0];
            const float p1 = __expf(s[jn][1] - mg[0]) * invl[0];
            const float p2 = __expf(s[jn][2] - mg[1]) * invl[1];
            const float p3 = __expf(s[jn][3] - mg[1]) * invl[1];
            const int col = jn * 8 + 2 * tig;
            *(float2*)(Ap + (size_t)r0 * HW + kt * 64 + col)       = make_float2(p0, p1);
            *(float2*)(Ap + (size_t)(r0 + 8) * HW + kt * 64 + col) = make_float2(p2, p3);
            Pw[g * 68 + col]           = f2tf(p0);
            Pw[g * 68 + col + 1]       = f2tf(p1);
            Pw[(g + 8) * 68 + col]     = f2tf(p2);
            Pw[(g + 8) * 68 + col + 1] = f2tf(p3);
        }
        __syncwarp();
        const unsigned* Vb = Vs + buf * 64 * 72;
        #pragma unroll
        for (int ks = 0; ks < 8; ks++) {
            const int kb = ks * 8 + tig;
            unsigned af[4];
            af[0] = Pw[g * 68 + kb];
            af[1] = Pw[(g + 8) * 68 + kb];
            af[2] = Pw[g * 68 + kb + 4];
            af[3] = Pw[(g + 8) * 68 + kb + 4];
            #pragma unroll
            for (int jn = 0; jn < 8; jn++) {
                const int n = jn * 8 + g;
                unsigned bf[2];
                bf[0] = Vb[kb * 72 + n];
                bf[1] = Vb[(kb + 4) * 72 + n];
                mma_tf32(o[jn], af, bf);
            }
        }
        __syncthreads();
    }
    #pragma unroll
    for (int jn = 0; jn < 8; jn++) {
        const int col = jn * 8 + 2 * tig;
        *(float2*)(Op + (size_t)r0 * 512 + col)       = make_float2(o[jn][0], o[jn][1]);
        *(float2*)(Op + (size_t)(r0 + 8) * 512 + col) = make_float2(o[jn][2], o[jn][3]);
    }
}

// =================================================================
__global__ void add_ao(const float4* __restrict__ a, float4* __restrict__ c) {
    const int i = blockIdx.x * 512 + threadIdx.x;
    const size_t STRIDE = (size_t)2048 * 512 / 4;
    float4 x = a[i], y = a[i + STRIDE], zc = a[i + 2 * STRIDE], wd = a[i + 3 * STRIDE];
    c[i] = make_float4(x.x + y.x + zc.x + wd.x, x.y + y.y + zc.y + wd.y,
                       x.z + y.z + zc.z + wd.z, x.w + y.w + zc.w + wd.w);
}

// =================================================================
__global__ void ln_kernel(const float* __restrict__ x, const float* __restrict__ g,
                          const float* __restrict__ bb, float* __restrict__ out) {
    __shared__ float red[8];
    const int row = blockIdx.x, t = threadIdx.x;
    const float* xr = x + (size_t)row * 512;
    const float v0 = xr[t], v1 = xr[t + 256];
    float s = v0 + v1;
    #pragma unroll
    for (int o = 16; o; o >>= 1) s += __shfl_xor_sync(0xffffffffu, s, o);
    if ((t & 31) == 0) red[t >> 5] = s;
    __syncthreads();
    float tot = 0.f;
    #pragma unroll
    for (int i = 0; i < 8; i++) tot += red[i];
    const float mu = tot * (1.0f / 512.0f);
    const float d0 = v0 - mu, d1 = v1 - mu;
    float q = d0 * d0 + d1 * d1;
    __syncthreads();
    #pragma unroll
    for (int o = 16; o; o >>= 1) q += __shfl_xor_sync(0xffffffffu, q, o);
    if ((t & 31) == 0) red[t >> 5] = q;
    __syncthreads();
    tot = 0.f;
    #pragma unroll
    for (int i = 0; i < 8; i++) tot += red[i];
    const float inv = rsqrtf(tot * (1.0f / 512.0f) + 1e-5f);
    out[(size_t)row * 512 + t]       = d0 * inv * g[t] + bb[t];
    out[(size_t)row * 512 + t + 256] = d1 * inv * g[t + 256] + bb[t + 256];
}

// =================================================================
static const int SMEM_PROJ_N = (2 * 128 * 36 + 2 * 32 * 136) * 4;
static const int SMEM_PROJ_H = (2 * 32 * 136 + 2 * 32 * 136) * 4;
static const int SMEM_P1 = 2 * 64 * 68 * 4;
static const int SMEM_P2 = (2 * 64 * 68 + 2 * 64 * 72 + 4 * 16 * 68) * 4;

extern "C" void kernel_launch(void* const* d_in, const int* in_sizes, int n_in,
                              void* d_out, int out_size) {
    const float* hidden = (const float*)d_in[0];
    const float* aux    = (const float*)d_in[1];
    const float* Wq = (const float*)d_in[2];
    const float* bq = (const float*)d_in[3];
    const float* Wk = (const float*)d_in[4];
    const float* bk = (const float*)d_in[5];
    const float* Wv = (const float*)d_in[6];
    const float* bv = (const float*)d_in[7];
    const float* Wo = (const float*)d_in[8];
    const float* bo = (const float*)d_in[9];
    const float* lng = (const float*)d_in[10];
    const float* lnb = (const float*)d_in[11];
    float* out = (float*)d_out;

    float *gq, *gk, *gv, *gao, *gaop, *gx, *gml;
    cudaGetSymbolAddress((void**)&gq,   g_q);
    cudaGetSymbolAddress((void**)&gk,   g_k);
    cudaGetSymbolAddress((void**)&gv,   g_v);
    cudaGetSymbolAddress((void**)&gao,  g_ao);
    cudaGetSymbolAddress((void**)&gaop, g_aop);
    cudaGetSymbolAddress((void**)&gx,   g_x);
    cudaGetSymbolAddress((void**)&gml,  g_ml);

    const size_t AUXOUT = (size_t)2048 * 512;
    const size_t ATTN_N = (size_t)64 * 256 * 4096;
    float* attn;
    if ((size_t)out_size >= AUXOUT + ATTN_N) attn = out + AUXOUT;
    else cudaGetSymbolAddress((void**)&attn, g_attn_fb);

    static bool attrs_set = false;
    if (!attrs_set) {
        cudaFuncSetAttribute((const void*)gemm128ca<false, false>, cudaFuncAttributeMaxDynamicSharedMemorySize, SMEM_PROJ_N);
        cudaFuncSetAttribute((const void*)gemm128ca<true, true>,   cudaFuncAttributeMaxDynamicSharedMemorySize, SMEM_PROJ_H);
        cudaFuncSetAttribute((const void*)flash_pass1,             cudaFuncAttributeMaxDynamicSharedMemorySize, SMEM_P1);
        cudaFuncSetAttribute((const void*)flash_pass2,             cudaFuncAttributeMaxDynamicSharedMemorySize, SMEM_P2);
        attrs_set = true;
    }

    // Q projection
    gemm128ca<false, false><<<dim3(4, 16), 128, SMEM_PROJ_N>>>(aux, Wq, bq, nullptr, gq);
    // K / V projections (tf32-rounded outputs)
    gemm128ca<true, true><<<dim3(4, 256), 128, SMEM_PROJ_H>>>(hidden, Wk, bk, nullptr, gk);
    gemm128ca<true, true><<<dim3(4, 256), 128, SMEM_PROJ_H>>>(hidden, Wv, bv, nullptr, gv);
    // attention, split over 4 key-quarters
    flash_pass1<<<dim3(4, 64, NSPL), 128, SMEM_P1>>>(gq, gk, gml);
    flash_pass2<<<dim3(4, 64, NSPL), 128, SMEM_P2>>>(gq, gk, gv, gml, attn, gaop);
    add_ao<<<512, 512>>>((const float4*)gaop, (float4*)gao);
    // out-proj + residual
    gemm128ca<false, false><<<dim3(4, 16), 128, SMEM_PROJ_N>>>(gao, Wo, bo, aux, gx);
    // LayerNorm
    ln_kernel<<<2048, 256>>>(gx, lng, lnb, out);
}

// round 6
// speedup vs baseline: 6.2755x; 1.0192x over previous
#include <cuda_runtime.h>
#include <cstddef>

#define HW    4096
#define NK    256
#define DIM   512
#define NSPL  4   // key splits for attention

// ---------------- scratch (no allocation allowed) ----------------
__device__ float g_hid [32768u * 512u];          // tf32-prepped hidden
__device__ float g_auxp[2048u  * 512u];          // tf32-prepped aux
__device__ float g_wq  [512u * 512u];
__device__ float g_wk  [512u * 512u];
__device__ float g_wv  [512u * 512u];
__device__ float g_wo  [512u * 512u];
__device__ float g_q [2048u  * 512u];            // scaled+rounded Q
__device__ float g_k [32768u * 512u];            // tf32-rounded K
__device__ float g_v [32768u * 512u];            // tf32-rounded V
__device__ float g_ao [2048u * 512u];            // tf32-rounded AV output
__device__ float g_aop[4u * 2048u * 512u];       // partial O per key-quarter
__device__ float g_x [2048u  * 512u];
__device__ float g_ml[64u * 4u * 4u * 64u * 2u];
__device__ float g_attn_fb[(size_t)64 * 256 * 4096];

// ---------------- helpers ----------------
__device__ __forceinline__ unsigned f2tf(float x) {
    unsigned r;
    asm("cvt.rna.tf32.f32 %0, %1;" : "=r"(r) : "f"(x));
    return r;
}
__device__ __forceinline__ float rtf(float x) { return __uint_as_float(f2tf(x)); }
__device__ __forceinline__ void mma_tf32(float* c, const unsigned* a, const unsigned* b) {
    asm volatile(
        "mma.sync.aligned.m16n8k8.row.col.f32.tf32.tf32.f32 "
        "{%0,%1,%2,%3}, {%4,%5,%6,%7}, {%8,%9}, {%0,%1,%2,%3};\n"
        : "+f"(c[0]), "+f"(c[1]), "+f"(c[2]), "+f"(c[3])
        : "r"(a[0]), "r"(a[1]), "r"(a[2]), "r"(a[3]), "r"(b[0]), "r"(b[1]));
}
__device__ __forceinline__ void cp16(void* dst, const void* src) {
    unsigned d = (unsigned)__cvta_generic_to_shared(dst);
    asm volatile("cp.async.cg.shared.global [%0], [%1], 16;" :: "r"(d), "l"(src));
}
__device__ __forceinline__ void cpcommit() { asm volatile("cp.async.commit_group;"); }
template<int N> __device__ __forceinline__ void cpwait() {
    asm volatile("cp.async.wait_group %0;" :: "n"(N));
}

// =================================================================
// Prep kernels: tf32-round whole buffers once.
// =================================================================
__global__ void prep_hid(const float4* __restrict__ src, float4* __restrict__ dst) {
    const size_t i = (size_t)blockIdx.x * 512 + threadIdx.x;
    float4 v = src[i];
    dst[i] = make_float4(rtf(v.x), rtf(v.y), rtf(v.z), rtf(v.w));
}
// segments: aux (262144 f4) | Wq | Wk | Wv | Wo (65536 f4 each)
__global__ void prep_small(const float4* __restrict__ aux,
                           const float4* __restrict__ wq, const float4* __restrict__ wk,
                           const float4* __restrict__ wv, const float4* __restrict__ wo,
                           float4* __restrict__ auxp,
                           float4* __restrict__ pwq, float4* __restrict__ pwk,
                           float4* __restrict__ pwv, float4* __restrict__ pwo) {
    size_t i = (size_t)blockIdx.x * 512 + threadIdx.x;
    const float4* s; float4* d;
    if (i < 262144)      { s = aux + i;            d = auxp + i; }
    else if (i < 327680) { s = wq + (i - 262144);  d = pwq + (i - 262144); }
    else if (i < 393216) { s = wk + (i - 327680);  d = pwk + (i - 327680); }
    else if (i < 458752) { s = wv + (i - 393216);  d = pwv + (i - 393216); }
    else                 { s = wo + (i - 458752);  d = pwo + (i - 458752); }
    float4 v = *s;
    *d = make_float4(rtf(v.x), rtf(v.y), rtf(v.z), rtf(v.w));
}

// =================================================================
// Projection GEMM (all inputs pre-rounded, no in-loop cvt).
// 128x128 CTA tile, BK=32, 4 warps (2m x 2n), warp tile 64x64.
// MODE: 0 = plain fp32 out, 1 = tf32-rounded out, 2 = tf32(0.125*v) out
// =================================================================
template<bool HID_A, int MODE>
__global__ __launch_bounds__(128, 2)
void gemm128ca(const float* __restrict__ A, const float* __restrict__ W,
               const float* __restrict__ bias, const float* __restrict__ resid,
               float* __restrict__ C)
{
    extern __shared__ float sm[];
    float* Abase = sm;
    float* Bbase = sm + (HID_A ? 2 * 32 * 136 : 2 * 128 * 36);

    const int tid = threadIdx.x;
    const int m0 = blockIdx.y * 128, j0 = blockIdx.x * 128;
    const int w = tid >> 5, lane = tid & 31, g = lane >> 2, tig = lane & 3;
    const int mw = (w >> 1) * 64, nw = (w & 1) * 64;

    auto loadA = [&](int buf, int c0) {
        if (HID_A) {
            float* dst = Abase + buf * 32 * 136;
            const int bb = m0 >> 12, n0 = m0 & 4095;
            #pragma unroll
            for (int i = 0; i < 8; i++) {
                int id = tid + i * 128;
                int k = id >> 5, m4 = (id & 31) * 4;
                cp16(dst + k * 136 + m4,
                     A + ((size_t)(bb * 512 + c0 + k)) * 4096 + n0 + m4);
            }
        } else {
            float* dst = Abase + buf * 128 * 36;
            #pragma unroll
            for (int i = 0; i < 8; i++) {
                int id = tid + i * 128;
                int m = id >> 3, c4 = (id & 7) * 4;
                cp16(dst + m * 36 + c4, A + (size_t)(m0 + m) * 512 + c0 + c4);
            }
        }
    };
    auto loadB = [&](int buf, int c0) {
        float* dst = Bbase + buf * 32 * 136;
        #pragma unroll
        for (int i = 0; i < 8; i++) {
            int id = tid + i * 128;
            int k = id >> 5, n4 = (id & 31) * 4;
            cp16(dst + k * 136 + n4, W + (size_t)(c0 + k) * 512 + j0 + n4);
        }
    };

    float acc[4][8][4];
    #pragma unroll
    for (int i = 0; i < 4; i++)
        #pragma unroll
        for (int j = 0; j < 8; j++)
            #pragma unroll
            for (int r = 0; r < 4; r++) acc[i][j][r] = 0.f;

    loadA(0, 0); loadB(0, 0); cpcommit();
    for (int t = 0; t < 16; t++) {
        const int buf = t & 1;
        if (t < 15) { loadA(buf ^ 1, (t + 1) * 32); loadB(buf ^ 1, (t + 1) * 32); cpcommit(); cpwait<1>(); }
        else cpwait<0>();
        __syncthreads();
        const float* As = HID_A ? (Abase + buf * 32 * 136) : (Abase + buf * 128 * 36);
        const float* Bs = Bbase + buf * 32 * 136;
        #pragma unroll
        for (int k8 = 0; k8 < 4; k8++) {
            const int kb = k8 * 8 + tig;
            unsigned af[4][4], bf[8][2];
            #pragma unroll
            for (int im = 0; im < 4; im++) {
                const int r = mw + im * 16 + g;
                if (HID_A) {
                    af[im][0] = __float_as_uint(As[kb * 136 + r]);
                    af[im][1] = __float_as_uint(As[kb * 136 + r + 8]);
                    af[im][2] = __float_as_uint(As[(kb + 4) * 136 + r]);
                    af[im][3] = __float_as_uint(As[(kb + 4) * 136 + r + 8]);
                } else {
                    af[im][0] = __float_as_uint(As[r * 36 + kb]);
                    af[im][1] = __float_as_uint(As[(r + 8) * 36 + kb]);
                    af[im][2] = __float_as_uint(As[r * 36 + kb + 4]);
                    af[im][3] = __float_as_uint(As[(r + 8) * 36 + kb + 4]);
                }
            }
            #pragma unroll
            for (int jn = 0; jn < 8; jn++) {
                const int n = nw + jn * 8 + g;
                bf[jn][0] = __float_as_uint(Bs[kb * 136 + n]);
                bf[jn][1] = __float_as_uint(Bs[(kb + 4) * 136 + n]);
            }
            #pragma unroll
            for (int im = 0; im < 4; im++)
                #pragma unroll
                for (int jn = 0; jn < 8; jn++)
                    mma_tf32(acc[im][jn], af[im], bf[jn]);
        }
        __syncthreads();
    }
    #pragma unroll
    for (int im = 0; im < 4; im++) {
        #pragma unroll
        for (int jn = 0; jn < 8; jn++) {
            const int r0 = m0 + mw + im * 16 + g;
            const int col = j0 + nw + jn * 8 + 2 * tig;
            const float* cc = acc[im][jn];
            #pragma unroll
            for (int half = 0; half < 2; half++) {
                const int r = r0 + half * 8;
                float v0 = cc[half * 2]     + bias[col];
                float v1 = cc[half * 2 + 1] + bias[col + 1];
                if (resid) {
                    v0 += resid[(size_t)r * 512 + col];
                    v1 += resid[(size_t)r * 512 + col + 1];
                }
                if (MODE == 1)      { v0 = rtf(v0); v1 = rtf(v1); }
                else if (MODE == 2) { v0 = rtf(0.125f * v0); v1 = rtf(0.125f * v1); }
                *(float2*)(C + (size_t)r * 512 + col) = make_float2(v0, v1);
            }
        }
    }
}

// =================================================================
// S tile mma helpers (all operands pre-rounded tf32 bits)
// =================================================================
__device__ __forceinline__ void mma_S(float s[8][4], const unsigned* Kbuf,
                                      const unsigned qf[8][4], int g, int tig) {
    #pragma unroll
    for (int jn = 0; jn < 8; jn++) { s[jn][0] = s[jn][1] = s[jn][2] = s[jn][3] = 0.f; }
    #pragma unroll
    for (int ks = 0; ks < 8; ks++) {
        const int kb = ks * 8 + tig;
        #pragma unroll
        for (int jn = 0; jn < 8; jn++) {
            unsigned bf[2];
            bf[0] = Kbuf[(jn * 8 + g) * 68 + kb];
            bf[1] = Kbuf[(jn * 8 + g) * 68 + kb + 4];
            mma_tf32(s[jn], qf[ks], bf);
        }
    }
}
__device__ __forceinline__ void load_qf(unsigned qf[8][4], const float* Qp, int r0, int tig) {
    #pragma unroll
    for (int ks = 0; ks < 8; ks++) {
        qf[ks][0] = __float_as_uint(Qp[(size_t)r0 * 512 + ks * 8 + tig]);
        qf[ks][1] = __float_as_uint(Qp[(size_t)(r0 + 8) * 512 + ks * 8 + tig]);
        qf[ks][2] = __float_as_uint(Qp[(size_t)r0 * 512 + ks * 8 + tig + 4]);
        qf[ks][3] = __float_as_uint(Qp[(size_t)(r0 + 8) * 512 + ks * 8 + tig + 4]);
    }
}

// =================================================================
// Pass 1: online row max / sum over 1024 keys. grid = (4, 64, 4)
// =================================================================
__global__ __launch_bounds__(128, 4)
void flash_pass1(const float* __restrict__ gq, const float* __restrict__ gk,
                 float* __restrict__ ml)
{
    extern __shared__ unsigned smu[];
    unsigned* Ks = smu;                      // [2][64][68]

    const int tid = threadIdx.x;
    const int w = tid >> 5, lane = tid & 31, g = lane >> 2, tig = lane & 3;
    const int z = blockIdx.y, b = z >> 3, h = z & 7;
    const int m0 = blockIdx.x * 64;
    const int qu = blockIdx.z;
    const float* Qp = gq + ((size_t)(b * 256 + m0)) * 512 + h * 64;
    const float* Kp = gk + (size_t)b * HW * 512 + h * 64 + (size_t)qu * 1024 * 512;
    const int r0 = w * 16 + g;

    unsigned qf[8][4];
    load_qf(qf, Qp, r0, tig);

    auto loadK = [&](int buf, int kt) {
        unsigned* dst = Ks + buf * 64 * 68;
        const float* src = Kp + (size_t)kt * 64 * 512;
        #pragma unroll
        for (int i = 0; i < 8; i++) {
            int id = tid + i * 128;
            int row = id >> 4, c4 = (id & 15) * 4;
            cp16(dst + row * 68 + c4, src + (size_t)row * 512 + c4);
        }
    };

    float m[2] = {-1e30f, -1e30f}, l[2] = {0.f, 0.f};

    loadK(0, 0); cpcommit();
    for (int kt = 0; kt < 16; kt++) {
        const int buf = kt & 1;
        if (kt < 15) { loadK(buf ^ 1, kt + 1); cpcommit(); cpwait<1>(); }
        else cpwait<0>();
        __syncthreads();
        float s[8][4];
        mma_S(s, Ks + buf * 64 * 68, qf, g, tig);
        #pragma unroll
        for (int rr = 0; rr < 2; rr++) {
            float mx = -1e30f;
            #pragma unroll
            for (int jn = 0; jn < 8; jn++)
                mx = fmaxf(mx, fmaxf(s[jn][2 * rr], s[jn][2 * rr + 1]));
            mx = fmaxf(mx, __shfl_xor_sync(0xffffffffu, mx, 1));
            mx = fmaxf(mx, __shfl_xor_sync(0xffffffffu, mx, 2));
            const float mn = fmaxf(m[rr], mx);
            float sum = 0.f;
            #pragma unroll
            for (int jn = 0; jn < 8; jn++)
                sum += __expf(s[jn][2 * rr] - mn) + __expf(s[jn][2 * rr + 1] - mn);
            sum += __shfl_xor_sync(0xffffffffu, sum, 1);
            sum += __shfl_xor_sync(0xffffffffu, sum, 2);
            l[rr] = l[rr] * __expf(m[rr] - mn) + sum;
            m[rr] = mn;
        }
        __syncthreads();
    }
    if (tig == 0) {
        float* dst = ml + (((size_t)(z * 4 + blockIdx.x) * NSPL + qu) * 64) * 2;
        dst[r0 * 2]           = m[0];
        dst[r0 * 2 + 1]       = l[0];
        dst[(r0 + 8) * 2]     = m[1];
        dst[(r0 + 8) * 2 + 1] = l[1];
    }
}

// =================================================================
// Pass 2: P = exp(S-m)/l -> attn; O += P @ V via register-shuffle A-frags
// (no P smem). grid = (4, 64, 4)
// =================================================================
__global__ __launch_bounds__(128, 3)
void flash_pass2(const float* __restrict__ gq, const float* __restrict__ gk,
                 const float* __restrict__ gv, const float* __restrict__ ml,
                 float* __restrict__ attn, float* __restrict__ aop)
{
    extern __shared__ unsigned smu[];
    unsigned* Ks = smu;                  // [2][64][68]
    unsigned* Vs = smu + 2 * 64 * 68;    // [2][64][72]

    const int tid = threadIdx.x;
    const int w = tid >> 5, lane = tid & 31, g = lane >> 2, tig = lane & 3;
    const int z = blockIdx.y, b = z >> 3, h = z & 7;
    const int m0 = blockIdx.x * 64;
    const int qu = blockIdx.z;
    const float* Qp = gq + ((size_t)(b * 256 + m0)) * 512 + h * 64;
    const float* Kp = gk + (size_t)b * HW * 512 + h * 64 + (size_t)qu * 1024 * 512;
    const float* Vp = gv + (size_t)b * HW * 512 + h * 64 + (size_t)qu * 1024 * 512;
    float* Ap = attn + (size_t)z * NK * HW + (size_t)m0 * HW + qu * 1024;
    float* Op = aop + (size_t)qu * 2048 * 512 + ((size_t)(b * 256 + m0)) * 512 + h * 64;
    const int r0 = w * 16 + g;

    unsigned qf[8][4];
    load_qf(qf, Qp, r0, tig);

    float mg[2], invl[2];
    {
        const float* mlb = ml + ((size_t)(z * 4 + blockIdx.x) * NSPL) * 128;
        #pragma unroll
        for (int rr = 0; rr < 2; rr++) {
            const int row = r0 + rr * 8;
            float mm = -1e30f;
            #pragma unroll
            for (int q = 0; q < NSPL; q++) mm = fmaxf(mm, mlb[q * 128 + row * 2]);
            float ll = 0.f;
            #pragma unroll
            for (int q = 0; q < NSPL; q++)
                ll += mlb[q * 128 + row * 2 + 1] * __expf(mlb[q * 128 + row * 2] - mm);
            mg[rr] = mm;
            invl[rr] = 1.f / ll;
        }
    }

    auto loadK = [&](int buf, int kt) {
        unsigned* dst = Ks + buf * 64 * 68;
        const float* src = Kp + (size_t)kt * 64 * 512;
        #pragma unroll
        for (int i = 0; i < 8; i++) {
            int id = tid + i * 128;
            int row = id >> 4, c4 = (id & 15) * 4;
            cp16(dst + row * 68 + c4, src + (size_t)row * 512 + c4);
        }
    };
    auto loadV = [&](int buf, int kt) {
        unsigned* dst = Vs + buf * 64 * 72;
        const float* src = Vp + (size_t)kt * 64 * 512;
        #pragma unroll
        for (int i = 0; i < 8; i++) {
            int id = tid + i * 128;
            int row = id >> 4, c4 = (id & 15) * 4;
            cp16(dst + row * 72 + c4, src + (size_t)row * 512 + c4);
        }
    };

    float o[8][4];
    #pragma unroll
    for (int jn = 0; jn < 8; jn++)
        #pragma unroll
        for (int r = 0; r < 4; r++) o[jn][r] = 0.f;

    const int src0 = (lane & ~3) | (tig >> 1);
    const int src1 = src0 + 2;
    const bool oddt = tig & 1;

    loadK(0, 0); loadV(0, 0); cpcommit();
    for (int kt = 0; kt < 16; kt++) {
        const int buf = kt & 1;
        if (kt < 15) { loadK(buf ^ 1, kt + 1); loadV(buf ^ 1, kt + 1); cpcommit(); cpwait<1>(); }
        else cpwait<0>();
        __syncthreads();
        float s[8][4];
        mma_S(s, Ks + buf * 64 * 68, qf, g, tig);
        const unsigned* Vb = Vs + buf * 64 * 72;
        #pragma unroll
        for (int ks = 0; ks < 8; ks++) {
            const float p0 = __expf(s[ks][0] - mg[0]) * invl[0];
            const float p1 = __expf(s[ks][1] - mg[0]) * invl[0];
            const float p2 = __expf(s[ks][2] - mg[1]) * invl[1];
            const float p3 = __expf(s[ks][3] - mg[1]) * invl[1];
            const int col = ks * 8 + 2 * tig;
            *(float2*)(Ap + (size_t)r0 * HW + kt * 64 + col)       = make_float2(p0, p1);
            *(float2*)(Ap + (size_t)(r0 + 8) * HW + kt * 64 + col) = make_float2(p2, p3);
            // redistribute P into A-operand fragment layout via shuffles
            const float a0 = __shfl_sync(0xffffffffu, p0, src0);
            const float b0 = __shfl_sync(0xffffffffu, p1, src0);
            const float c0 = __shfl_sync(0xffffffffu, p0, src1);
            const float d0 = __shfl_sync(0xffffffffu, p1, src1);
            const float a1 = __shfl_sync(0xffffffffu, p2, src0);
            const float b1 = __shfl_sync(0xffffffffu, p3, src0);
            const float c1 = __shfl_sync(0xffffffffu, p2, src1);
            const float d1 = __shfl_sync(0xffffffffu, p3, src1);
            unsigned af[4];
            af[0] = f2tf(oddt ? b0 : a0);
            af[1] = f2tf(oddt ? b1 : a1);
            af[2] = f2tf(oddt ? d0 : c0);
            af[3] = f2tf(oddt ? d1 : c1);
            const int kb = ks * 8 + tig;
            #pragma unroll
            for (int jn = 0; jn < 8; jn++) {
                const int n = jn * 8 + g;
                unsigned bf[2];
                bf[0] = Vb[kb * 72 + n];
                bf[1] = Vb[(kb + 4) * 72 + n];
                mma_tf32(o[jn], af, bf);
            }
        }
        __syncthreads();
    }
    #pragma unroll
    for (int jn = 0; jn < 8; jn++) {
        const int col = jn * 8 + 2 * tig;
        *(float2*)(Op + (size_t)r0 * 512 + col)       = make_float2(o[jn][0], o[jn][1]);
        *(float2*)(Op + (size_t)(r0 + 8) * 512 + col) = make_float2(o[jn][2], o[jn][3]);
    }
}

// =================================================================
__global__ void add_ao(const float4* __restrict__ a, float4* __restrict__ c) {
    const int i = blockIdx.x * 512 + threadIdx.x;
    const size_t STRIDE = (size_t)2048 * 512 / 4;
    float4 x = a[i], y = a[i + STRIDE], zc = a[i + 2 * STRIDE], wd = a[i + 3 * STRIDE];
    c[i] = make_float4(rtf(x.x + y.x + zc.x + wd.x), rtf(x.y + y.y + zc.y + wd.y),
                       rtf(x.z + y.z + zc.z + wd.z), rtf(x.w + y.w + zc.w + wd.w));
}

// =================================================================
__global__ void ln_kernel(const float* __restrict__ x, const float* __restrict__ g,
                          const float* __restrict__ bb, float* __restrict__ out) {
    __shared__ float red[8];
    const int row = blockIdx.x, t = threadIdx.x;
    const float* xr = x + (size_t)row * 512;
    const float v0 = xr[t], v1 = xr[t + 256];
    float s = v0 + v1;
    #pragma unroll
    for (int o = 16; o; o >>= 1) s += __shfl_xor_sync(0xffffffffu, s, o);
    if ((t & 31) == 0) red[t >> 5] = s;
    __syncthreads();
    float tot = 0.f;
    #pragma unroll
    for (int i = 0; i < 8; i++) tot += red[i];
    const float mu = tot * (1.0f / 512.0f);
    const float d0 = v0 - mu, d1 = v1 - mu;
    float q = d0 * d0 + d1 * d1;
    __syncthreads();
    #pragma unroll
    for (int o = 16; o; o >>= 1) q += __shfl_xor_sync(0xffffffffu, q, o);
    if ((t & 31) == 0) red[t >> 5] = q;
    __syncthreads();
    tot = 0.f;
    #pragma unroll
    for (int i = 0; i < 8; i++) tot += red[i];
    const float inv = rsqrtf(tot * (1.0f / 512.0f) + 1e-5f);
    out[(size_t)row * 512 + t]       = d0 * inv * g[t] + bb[t];
    out[(size_t)row * 512 + t + 256] = d1 * inv * g[t + 256] + bb[t + 256];
}

// =================================================================
static const int SMEM_PROJ_N = (2 * 128 * 36 + 2 * 32 * 136) * 4;
static const int SMEM_PROJ_H = (2 * 32 * 136 + 2 * 32 * 136) * 4;
static const int SMEM_P1 = 2 * 64 * 68 * 4;
static const int SMEM_P2 = (2 * 64 * 68 + 2 * 64 * 72) * 4;

extern "C" void kernel_launch(void* const* d_in, const int* in_sizes, int n_in,
                              void* d_out, int out_size) {
    const float* hidden = (const float*)d_in[0];
    const float* aux    = (const float*)d_in[1];
    const float* Wq = (const float*)d_in[2];
    const float* bq = (const float*)d_in[3];
    const float* Wk = (const float*)d_in[4];
    const float* bk = (const float*)d_in[5];
    const float* Wv = (const float*)d_in[6];
    const float* bv = (const float*)d_in[7];
    const float* Wo = (const float*)d_in[8];
    const float* bo = (const float*)d_in[9];
    const float* lng = (const float*)d_in[10];
    const float* lnb = (const float*)d_in[11];
    float* out = (float*)d_out;

    float *ghid, *gauxp, *gwq, *gwk, *gwv, *gwo;
    float *gq, *gk, *gv, *gao, *gaop, *gx, *gml;
    cudaGetSymbolAddress((void**)&ghid,  g_hid);
    cudaGetSymbolAddress((void**)&gauxp, g_auxp);
    cudaGetSymbolAddress((void**)&gwq,   g_wq);
    cudaGetSymbolAddress((void**)&gwk,   g_wk);
    cudaGetSymbolAddress((void**)&gwv,   g_wv);
    cudaGetSymbolAddress((void**)&gwo,   g_wo);
    cudaGetSymbolAddress((void**)&gq,    g_q);
    cudaGetSymbolAddress((void**)&gk,    g_k);
    cudaGetSymbolAddress((void**)&gv,    g_v);
    cudaGetSymbolAddress((void**)&gao,   g_ao);
    cudaGetSymbolAddress((void**)&gaop,  g_aop);
    cudaGetSymbolAddress((void**)&gx,    g_x);
    cudaGetSymbolAddress((void**)&gml,   g_ml);

    const size_t AUXOUT = (size_t)2048 * 512;
    const size_t ATTN_N = (size_t)64 * 256 * 4096;
    float* attn;
    if ((size_t)out_size >= AUXOUT + ATTN_N) attn = out + AUXOUT;
    else cudaGetSymbolAddress((void**)&attn, g_attn_fb);

    static bool attrs_set = false;
    if (!attrs_set) {
        cudaFuncSetAttribute((const void*)gemm128ca<false, 0>, cudaFuncAttributeMaxDynamicSharedMemorySize, SMEM_PROJ_N);
        cudaFuncSetAttribute((const void*)gemm128ca<false, 2>, cudaFuncAttributeMaxDynamicSharedMemorySize, SMEM_PROJ_N);
        cudaFuncSetAttribute((const void*)gemm128ca<true, 1>,  cudaFuncAttributeMaxDynamicSharedMemorySize, SMEM_PROJ_H);
        cudaFuncSetAttribute((const void*)flash_pass1,         cudaFuncAttributeMaxDynamicSharedMemorySize, SMEM_P1);
        cudaFuncSetAttribute((const void*)flash_pass2,         cudaFuncAttributeMaxDynamicSharedMemorySize, SMEM_P2);
        attrs_set = true;
    }

    // prep: tf32-round inputs
    prep_hid<<<8192, 512>>>((const float4*)hidden, (float4*)ghid);
    prep_small<<<1024, 512>>>((const float4*)aux, (const float4*)Wq, (const float4*)Wk,
                              (const float4*)Wv, (const float4*)Wo,
                              (float4*)gauxp, (float4*)gwq, (float4*)gwk,
                              (float4*)gwv, (float4*)gwo);

    // Q projection (scaled + rounded output)
    gemm128ca<false, 2><<<dim3(4, 16), 128, SMEM_PROJ_N>>>(gauxp, gwq, bq, nullptr, gq);
    // K / V projections (rounded outputs)
    gemm128ca<true, 1><<<dim3(4, 256), 128, SMEM_PROJ_H>>>(ghid, gwk, bk, nullptr, gk);
    gemm128ca<true, 1><<<dim3(4, 256), 128, SMEM_PROJ_H>>>(ghid, gwv, bv, nullptr, gv);
    // attention
    flash_pass1<<<dim3(4, 64, NSPL), 128, SMEM_P1>>>(gq, gk, gml);
    flash_pass2<<<dim3(4, 64, NSPL), 128, SMEM_P2>>>(gq, gk, gv, gml, attn, gaop);
    add_ao<<<512, 512>>>((const float4*)gaop, (float4*)gao);
    // out-proj + residual (resid = original aux, fp32)
    gemm128ca<false, 0><<<dim3(4, 16), 128, SMEM_PROJ_N>>>(gao, gwo, bo, aux, gx);
    // LayerNorm
    ln_kernel<<<2048, 256>>>(gx, lng, lnb, out);
}